// round 5
// baseline (speedup 1.0000x reference)
#include <cuda_runtime.h>

// Problem constants
#define BB   16384
#define S    17
#define V    29
#define D    128
#define NSEG 4
#define NL   6
#define EPS  1e-5f

// Tiling
#define BQ       4              // batches per CTA
#define ROWS     (BQ * S)       // 68
#define NTHREADS 544            // 17 warps: 68 rows / 4 rows-per-warp exactly
#define NWARPS   17
#define CHUNK_K  32             // k-rows per weight stage chunk
#define NCHUNK   (D / CHUNK_K)  // 4
#define WBUF     (CHUNK_K * D)  // 4096 floats per chunk buffer

// Shared memory layout (float offsets)
#define OFF_X   0                        // x residual   [68][128]
#define OFF_Q   8704                     // q / attn scratch
#define OFF_K   17408                    // k scratch
#define OFF_V   26112                    // v scratch
#define OFF_W   34816                    // 3 weight chunk buffers [3][32][128]
#define OFF_SC  47104                    // scores [4][17][17]
#define OFF_M   48260                    // mask [68]
#define OFF_SEG 48328                    // seg one-hot [68][4]
#define SMEM_FLOATS 48600
#define SMEM_BYTES  (SMEM_FLOATS * 4)    // 194,400 B

#define FMA4(_acc_, _s_, _w_)                                                  \
    _acc_.x += (_s_) * (_w_).x; _acc_.y += (_s_) * (_w_).y;                    \
    _acc_.z += (_s_) * (_w_).z; _acc_.w += (_s_) * (_w_).w;

#define RELU4(_a_)                                                             \
    _a_.x = fmaxf(_a_.x, 0.f); _a_.y = fmaxf(_a_.y, 0.f);                      \
    _a_.z = fmaxf(_a_.z, 0.f); _a_.w = fmaxf(_a_.w, 0.f);

// x[r] = LN(x[r] + add[r]) * g + b   (4 rows per warp)
__device__ __forceinline__ void ln_add(float* __restrict__ sx,
                                       const float* __restrict__ add,
                                       const float* __restrict__ g,
                                       const float* __restrict__ b,
                                       int warp, int lane) {
    const int c = lane * 4;
    const float4 gv = *(const float4*)&g[c];
    const float4 bvec = *(const float4*)&b[c];
    for (int r = warp; r < ROWS; r += NWARPS) {
        const float4 xv = *(const float4*)&sx[r * D + c];
        const float4 av = *(const float4*)&add[r * D + c];
        float4 t;
        t.x = xv.x + av.x; t.y = xv.y + av.y; t.z = xv.z + av.z; t.w = xv.w + av.w;
        float s  = t.x + t.y + t.z + t.w;
        float sq = t.x * t.x + t.y * t.y + t.z * t.z + t.w * t.w;
#pragma unroll
        for (int o = 16; o; o >>= 1) {
            s  += __shfl_xor_sync(0xFFFFFFFFu, s,  o);
            sq += __shfl_xor_sync(0xFFFFFFFFu, sq, o);
        }
        const float mu  = s * (1.0f / D);
        const float var = sq * (1.0f / D) - mu * mu;
        const float inv = rsqrtf(var + EPS);
        float4 o4;
        o4.x = (t.x - mu) * inv * gv.x + bvec.x;
        o4.y = (t.y - mu) * inv * gv.y + bvec.y;
        o4.z = (t.z - mu) * inv * gv.z + bvec.z;
        o4.w = (t.w - mu) * inv * gv.w + bvec.w;
        *(float4*)&sx[r * D + c] = o4;
    }
}

// ---------------------------------------------------------------------------
__global__ __launch_bounds__(NTHREADS, 1)
void artistbert_kernel(const float* __restrict__ X,    const float* __restrict__ mask_in,
                       const float* __restrict__ seg_in,
                       const float* __restrict__ We,   const float* __restrict__ be,
                       const float* __restrict__ Wp,   const float* __restrict__ bp,
                       const float* __restrict__ Wsg,  const float* __restrict__ bsg,
                       const float* __restrict__ g1,   const float* __restrict__ b1,
                       const float* __restrict__ Wq,   const float* __restrict__ bq,
                       const float* __restrict__ Wk,   const float* __restrict__ bk,
                       const float* __restrict__ Wv,   const float* __restrict__ bv,
                       const float* __restrict__ g2,   const float* __restrict__ b2,
                       const float* __restrict__ Wd,   const float* __restrict__ bd,
                       const float* __restrict__ Wo,   const float* __restrict__ bo,
                       float* __restrict__ out) {
    extern __shared__ float sm[];
    float* sx    = sm + OFF_X;
    float* sq    = sm + OFF_Q;
    float* sk    = sm + OFF_K;
    float* sv    = sm + OFF_V;
    float* sw0   = sm + OFF_W;
    float* sw1   = sm + OFF_W + WBUF;
    float* sw2   = sm + OFF_W + 2 * WBUF;
    float* ss    = sm + OFF_SC;
    float* smask = sm + OFF_M;
    float* sseg  = sm + OFF_SEG;

    const int tid  = threadIdx.x;
    const int warp = tid >> 5;
    const int lane = tid & 31;
    const int c4   = lane * 4;
    const int  b0       = blockIdx.x * BQ;
    const long base_row = (long)b0 * S;

    // row pointers for this warp's 4 rows
    float* xr0 = sx + (4 * warp + 0) * D;
    float* xr1 = sx + (4 * warp + 1) * D;
    float* xr2 = sx + (4 * warp + 2) * D;
    float* xr3 = sx + (4 * warp + 3) * D;

    // ---- stage embedding tables + per-tile inputs ----
    for (int i = tid; i < V * D; i += NTHREADS) sw0[i] = We[i];      // We -> W area
    for (int i = tid; i < S * D; i += NTHREADS) {
        const int d = i & (D - 1);
        sq[i] = Wp[i] + bp[d] + be[d] + bsg[d];                      // combined pos+biases
    }
    for (int i = tid; i < NSEG * D; i += NTHREADS) sq[S * D + i] = Wsg[i];
    {
        const float* Xb = X + base_row * V;
        for (int i = tid; i < ROWS * V; i += NTHREADS) sv[i] = Xb[i];
    }
    for (int i = tid; i < ROWS; i += NTHREADS) smask[i] = mask_in[base_row + i];
    {
        const float* Sg = seg_in + base_row * NSEG;
        for (int i = tid; i < ROWS * NSEG; i += NTHREADS) sseg[i] = Sg[i];
    }
    __syncthreads();

    // ---- embedding: sx = X@We + posc + seg@Wsg ----
    for (int r = warp; r < ROWS; r += NWARPS) {
        const int s = r % S;
        float4 acc = *(const float4*)&sq[s * D + c4];
#pragma unroll
        for (int j = 0; j < NSEG; ++j) {
            const float svv = sseg[r * NSEG + j];
            const float4 wv = *(const float4*)&sq[S * D + j * D + c4];
            FMA4(acc, svv, wv)
        }
        const float* xr = &sv[r * V];
#pragma unroll
        for (int vtok = 0; vtok < V; ++vtok) {
            const float xv = xr[vtok];
            const float4 wv = *(const float4*)&sw0[vtok * D + c4];
            FMA4(acc, xv, wv)
        }
        *(float4*)&sx[r * D + c4] = acc;
    }
    __syncthreads();

    // ---- transformer layers ----
    for (int li = 0; li < NL; ++li) {
        const float* gWq = Wq + li * D * D;
        const float* gWk = Wk + li * D * D;
        const float* gWv = Wv + li * D * D;

        // ================= joint Q/K/V GEMM (x loaded once) =================
        {
            float4 aq0, aq1, aq2, aq3, ak0, ak1, ak2, ak3, av0, av1, av2, av3;
            {
                const float4 bvq = *(const float4*)&bq[li * D + c4];
                const float4 bvk = *(const float4*)&bk[li * D + c4];
                const float4 bvv = *(const float4*)&bv[li * D + c4];
                aq0 = aq1 = aq2 = aq3 = bvq;
                ak0 = ak1 = ak2 = ak3 = bvk;
                av0 = av1 = av2 = av3 = bvv;
            }
            // prefetch chunk 0 into registers (1024 float4 per matrix chunk)
            float4 pq_a, pq_b, pk_a, pk_b, pv_a, pv_b;
            {
                const float4* q4 = (const float4*)gWq;
                const float4* k4 = (const float4*)gWk;
                const float4* v4 = (const float4*)gWv;
                pq_a = q4[tid]; pk_a = k4[tid]; pv_a = v4[tid];
                if (tid < WBUF / 4 - NTHREADS) {
                    pq_b = q4[tid + NTHREADS]; pk_b = k4[tid + NTHREADS]; pv_b = v4[tid + NTHREADS];
                }
            }
            for (int ch = 0; ch < NCHUNK; ++ch) {
                __syncthreads();   // previous chunk consumed by everyone
                // store prefetched chunk
                ((float4*)sw0)[tid] = pq_a;
                ((float4*)sw1)[tid] = pk_a;
                ((float4*)sw2)[tid] = pv_a;
                if (tid < WBUF / 4 - NTHREADS) {
                    ((float4*)sw0)[tid + NTHREADS] = pq_b;
                    ((float4*)sw1)[tid + NTHREADS] = pk_b;
                    ((float4*)sw2)[tid + NTHREADS] = pv_b;
                }
                // prefetch next chunk (latency hidden behind FFMA below)
                if (ch + 1 < NCHUNK) {
                    const float4* q4 = (const float4*)(gWq + (ch + 1) * WBUF);
                    const float4* k4 = (const float4*)(gWk + (ch + 1) * WBUF);
                    const float4* v4 = (const float4*)(gWv + (ch + 1) * WBUF);
                    pq_a = q4[tid]; pk_a = k4[tid]; pv_a = v4[tid];
                    if (tid < WBUF / 4 - NTHREADS) {
                        pq_b = q4[tid + NTHREADS]; pk_b = k4[tid + NTHREADS]; pv_b = v4[tid + NTHREADS];
                    }
                }
                __syncthreads();   // chunk visible
                const int kbase = ch * CHUNK_K;
#pragma unroll 2
                for (int kl = 0; kl < CHUNK_K; kl += 4) {
                    const float4 v0 = *(const float4*)(xr0 + kbase + kl);
                    const float4 v1 = *(const float4*)(xr1 + kbase + kl);
                    const float4 v2 = *(const float4*)(xr2 + kbase + kl);
                    const float4 v3 = *(const float4*)(xr3 + kbase + kl);
#pragma unroll
                    for (int j = 0; j < 4; ++j) {
                        const float4 wq4 = *(const float4*)&sw0[(kl + j) * D + c4];
                        const float4 wk4 = *(const float4*)&sw1[(kl + j) * D + c4];
                        const float4 wv4 = *(const float4*)&sw2[(kl + j) * D + c4];
                        const float s0 = j == 0 ? v0.x : j == 1 ? v0.y : j == 2 ? v0.z : v0.w;
                        const float s1 = j == 0 ? v1.x : j == 1 ? v1.y : j == 2 ? v1.z : v1.w;
                        const float s2 = j == 0 ? v2.x : j == 1 ? v2.y : j == 2 ? v2.z : v2.w;
                        const float s3 = j == 0 ? v3.x : j == 1 ? v3.y : j == 2 ? v3.z : v3.w;
                        FMA4(aq0, s0, wq4) FMA4(aq1, s1, wq4) FMA4(aq2, s2, wq4) FMA4(aq3, s3, wq4)
                        FMA4(ak0, s0, wk4) FMA4(ak1, s1, wk4) FMA4(ak2, s2, wk4) FMA4(ak3, s3, wk4)
                        FMA4(av0, s0, wv4) FMA4(av1, s1, wv4) FMA4(av2, s2, wv4) FMA4(av3, s3, wv4)
                    }
                }
            }
            RELU4(aq0) RELU4(aq1) RELU4(aq2) RELU4(aq3)
            RELU4(ak0) RELU4(ak1) RELU4(ak2) RELU4(ak3)
            RELU4(av0) RELU4(av1) RELU4(av2) RELU4(av3)
            *(float4*)&sq[(4 * warp + 0) * D + c4] = aq0;
            *(float4*)&sq[(4 * warp + 1) * D + c4] = aq1;
            *(float4*)&sq[(4 * warp + 2) * D + c4] = aq2;
            *(float4*)&sq[(4 * warp + 3) * D + c4] = aq3;
            *(float4*)&sk[(4 * warp + 0) * D + c4] = ak0;
            *(float4*)&sk[(4 * warp + 1) * D + c4] = ak1;
            *(float4*)&sk[(4 * warp + 2) * D + c4] = ak2;
            *(float4*)&sk[(4 * warp + 3) * D + c4] = ak3;
            *(float4*)&sv[(4 * warp + 0) * D + c4] = av0;
            *(float4*)&sv[(4 * warp + 1) * D + c4] = av1;
            *(float4*)&sv[(4 * warp + 2) * D + c4] = av2;
            *(float4*)&sv[(4 * warp + 3) * D + c4] = av3;
        }
        __syncthreads();

        // scores[b][qi][ki] = q.k (warp per dot; 1156/17 = 68 per warp)
        for (int idx = warp; idx < BQ * S * S; idx += NWARPS) {
            const int b   = idx / (S * S);
            const int rem = idx - b * S * S;
            const int qi  = rem / S;
            const int ki  = rem - qi * S;
            const float4 qv = *(const float4*)&sq[(b * S + qi) * D + c4];
            const float4 kv = *(const float4*)&sk[(b * S + ki) * D + c4];
            float p = qv.x * kv.x + qv.y * kv.y + qv.z * kv.z + qv.w * kv.w;
#pragma unroll
            for (int o = 16; o; o >>= 1) p += __shfl_xor_sync(0xFFFFFFFFu, p, o);
            if (lane == 0) ss[idx] = p;
        }
        __syncthreads();

        // softmax over last dim (thread per (b,qi) row)
        if (tid < ROWS) {
            float* row = &ss[(tid / S) * S * S + (tid % S) * S];
            float mx = row[0];
#pragma unroll
            for (int j = 1; j < S; ++j) mx = fmaxf(mx, row[j]);
            float sum = 0.f;
#pragma unroll
            for (int j = 0; j < S; ++j) { const float e = __expf(row[j] - mx); row[j] = e; sum += e; }
            const float inv = 1.0f / sum;
#pragma unroll
            for (int j = 0; j < S; ++j) row[j] *= inv;
        }
        __syncthreads();

        // attn = (scores @ v) * mask -> sq (q dead after scores)
        for (int r = warp; r < ROWS; r += NWARPS) {
            const int b  = r / S;
            const int qi = r - b * S;
            const float* p  = &ss[b * S * S + qi * S];
            const float* vb = &sv[(b * S) * D];
            float4 acc = make_float4(0.f, 0.f, 0.f, 0.f);
#pragma unroll
            for (int ki = 0; ki < S; ++ki) {
                const float pv = p[ki];
                const float4 vv = *(const float4*)&vb[ki * D + c4];
                FMA4(acc, pv, vv)
            }
            const float m = smask[r];
            acc.x *= m; acc.y *= m; acc.z *= m; acc.w *= m;
            *(float4*)&sq[r * D + c4] = acc;
        }
        __syncthreads();

        // x = LN(x + attn)
        ln_add(sx, sq, g1 + li * D, b1 + li * D, warp, lane);
        __syncthreads();

        // ================= d = x@Wd + bd (chunked, prefetched) ==============
        {
            const float* gWd = Wd + li * D * D;
            float4 a0, a1, a2, a3;
            {
                const float4 bvd = *(const float4*)&bd[li * D + c4];
                a0 = a1 = a2 = a3 = bvd;
            }
            float4 pd_a, pd_b;
            {
                const float4* d4 = (const float4*)gWd;
                pd_a = d4[tid];
                if (tid < WBUF / 4 - NTHREADS) pd_b = d4[tid + NTHREADS];
            }
            for (int ch = 0; ch < NCHUNK; ++ch) {
                __syncthreads();
                ((float4*)sw0)[tid] = pd_a;
                if (tid < WBUF / 4 - NTHREADS) ((float4*)sw0)[tid + NTHREADS] = pd_b;
                if (ch + 1 < NCHUNK) {
                    const float4* d4 = (const float4*)(gWd + (ch + 1) * WBUF);
                    pd_a = d4[tid];
                    if (tid < WBUF / 4 - NTHREADS) pd_b = d4[tid + NTHREADS];
                }
                __syncthreads();
                const int kbase = ch * CHUNK_K;
#pragma unroll 2
                for (int kl = 0; kl < CHUNK_K; kl += 4) {
                    const float4 v0 = *(const float4*)(xr0 + kbase + kl);
                    const float4 v1 = *(const float4*)(xr1 + kbase + kl);
                    const float4 v2 = *(const float4*)(xr2 + kbase + kl);
                    const float4 v3 = *(const float4*)(xr3 + kbase + kl);
#pragma unroll
                    for (int j = 0; j < 4; ++j) {
                        const float4 w4 = *(const float4*)&sw0[(kl + j) * D + c4];
                        const float s0 = j == 0 ? v0.x : j == 1 ? v0.y : j == 2 ? v0.z : v0.w;
                        const float s1 = j == 0 ? v1.x : j == 1 ? v1.y : j == 2 ? v1.z : v1.w;
                        const float s2 = j == 0 ? v2.x : j == 1 ? v2.y : j == 2 ? v2.z : v2.w;
                        const float s3 = j == 0 ? v3.x : j == 1 ? v3.y : j == 2 ? v3.z : v3.w;
                        FMA4(a0, s0, w4) FMA4(a1, s1, w4) FMA4(a2, s2, w4) FMA4(a3, s3, w4)
                    }
                }
            }
            *(float4*)&sq[(4 * warp + 0) * D + c4] = a0;
            *(float4*)&sq[(4 * warp + 1) * D + c4] = a1;
            *(float4*)&sq[(4 * warp + 2) * D + c4] = a2;
            *(float4*)&sq[(4 * warp + 3) * D + c4] = a3;
        }
        __syncthreads();

        // x = LN(x + d)
        ln_add(sx, sq, g2 + li * D, b2 + li * D, warp, lane);
        __syncthreads();
    }

    // ---- output projection: out = x@Wo + bo ----
    for (int i = tid; i < D * 32; i += NTHREADS) {
        const int k = i >> 5, n = i & 31;
        sw0[i] = (n < V) ? Wo[k * V + n] : 0.f;
    }
    __syncthreads();
    for (int r = warp; r < ROWS; r += NWARPS) {
        if (lane < V) {
            float acc = bo[lane];
            const float* xr = &sx[r * D];
#pragma unroll 8
            for (int k = 0; k < D; ++k) acc += xr[k] * sw0[k * 32 + lane];
            out[(base_row + r) * V + lane] = acc;
        }
    }
}

// ---------------------------------------------------------------------------
extern "C" void kernel_launch(void* const* d_in, const int* in_sizes, int n_in,
                              void* d_out, int out_size) {
    (void)in_sizes; (void)n_in; (void)out_size;
    const float* X    = (const float*)d_in[0];
    const float* mask = (const float*)d_in[1];
    const float* seg  = (const float*)d_in[2];
    const float* We   = (const float*)d_in[3];
    const float* be   = (const float*)d_in[4];
    const float* Wp   = (const float*)d_in[5];
    const float* bp   = (const float*)d_in[6];
    const float* Wsg  = (const float*)d_in[7];
    const float* bsg  = (const float*)d_in[8];
    const float* g1   = (const float*)d_in[9];
    const float* b1   = (const float*)d_in[10];
    const float* Wq   = (const float*)d_in[11];
    const float* bq   = (const float*)d_in[12];
    const float* Wk   = (const float*)d_in[13];
    const float* bk   = (const float*)d_in[14];
    const float* Wv   = (const float*)d_in[15];
    const float* bv   = (const float*)d_in[16];
    const float* g2   = (const float*)d_in[17];
    const float* b2   = (const float*)d_in[18];
    const float* Wd   = (const float*)d_in[19];
    const float* bd   = (const float*)d_in[20];
    const float* Wo   = (const float*)d_in[21];
    const float* bo   = (const float*)d_in[22];
    float* out = (float*)d_out;

    cudaFuncSetAttribute(artistbert_kernel,
                         cudaFuncAttributeMaxDynamicSharedMemorySize, SMEM_BYTES);

    artistbert_kernel<<<BB / BQ, NTHREADS, SMEM_BYTES>>>(
        X, mask, seg, We, be, Wp, bp, Wsg, bsg, g1, b1,
        Wq, bq, Wk, bk, Wv, bv, g2, b2, Wd, bd, Wo, bo, out);
}

// round 7
// speedup vs baseline: 1.0522x; 1.0522x over previous
#include <cuda_runtime.h>
#include <cstdint>

// Problem constants
#define BB   16384
#define S    17
#define V    29
#define D    128
#define NSEG 4
#define NL   6
#define EPS  1e-5f

// Tiling
#define BQ       4
#define ROWS     (BQ * S)       // 68
#define NTHREADS 640            // 20 warps = 5 Mtiles x 4 Ngroups
#define NWARPS   20
#define XS       132            // x/q/k/v row stride (132 % 32 == 4 -> A-frag conflict-free)
#define WS       136            // W row stride   (136 % 32 == 8 -> B-frag conflict-free)

// Shared memory layout (float offsets)
#define OFF_WB  0                        // W stage [128][136]
#define OFF_X   17408                    // x  [68][132]
#define OFF_Q   26384
#define OFF_K   35360
#define OFF_V   44336
#define OFF_SC  53312                    // scores [4][17][17]
#define OFF_M   54468
#define OFF_SEG 54536
#define SMEM_FLOATS 54808
#define SMEM_BYTES  (SMEM_FLOATS * 4)    // 219,232 B

#define FMA4(_acc_, _s_, _w_)                                                  \
    _acc_.x += (_s_) * (_w_).x; _acc_.y += (_s_) * (_w_).y;                    \
    _acc_.z += (_s_) * (_w_).z; _acc_.w += (_s_) * (_w_).w;

// ---------------------------------------------------------------------------
// tf32 helpers
// ---------------------------------------------------------------------------
__device__ __forceinline__ void tf32_split(float x, uint32_t& hi, uint32_t& lo) {
    uint32_t h;
    asm("cvt.rna.tf32.f32 %0, %1;" : "=r"(h) : "f"(x));
    const float r = x - __uint_as_float(h);
    uint32_t l;
    asm("cvt.rna.tf32.f32 %0, %1;" : "=r"(l) : "f"(r));
    hi = h; lo = l;
}

__device__ __forceinline__ void mma_tf32(float* d, const uint32_t* a, const uint32_t* b) {
    asm volatile(
        "mma.sync.aligned.m16n8k8.row.col.f32.tf32.tf32.f32 "
        "{%0,%1,%2,%3}, {%4,%5,%6,%7}, {%8,%9}, {%0,%1,%2,%3};"
        : "+f"(d[0]), "+f"(d[1]), "+f"(d[2]), "+f"(d[3])
        : "r"(a[0]), "r"(a[1]), "r"(a[2]), "r"(a[3]), "r"(b[0]), "r"(b[1]));
}

// Stage a 128x128 fp32 W (row-major [k][n]) into smem with row stride WS.
__device__ __forceinline__ void load_w(const float* __restrict__ g,
                                       float* __restrict__ swb, int tid) {
    const float4* g4 = (const float4*)g;
    float4* d4 = (float4*)swb;       // WS/4 = 34 float4 per row
    for (int i = tid; i < D * 32; i += NTHREADS) {
        const int k = i >> 5, n4 = i & 31;
        d4[k * 34 + n4] = g4[k * 32 + n4];
    }
}

// dst[r][n] = (relu?) src[r][:] . W[:][n] + bias[n]  via tf32 3-pass mma.
// warp = mt*4 + ng: mt in 0..4 (16-row tile), ng in 0..3 (32-col group).
template <bool RELU>
__device__ __forceinline__ void gemm_mma(const float* __restrict__ sx,
                                         const float* __restrict__ swb,
                                         const float* __restrict__ bias,
                                         float* __restrict__ dst,
                                         int warp, int lane) {
    const int mt = warp >> 2;
    const int ng = warp & 3;
    const int g  = lane >> 2;         // 0..7
    const int t  = lane & 3;          // 0..3
    const int r0 = mt * 16;
    const int n0 = ng * 32;
    const int ra = r0 + g, rb = r0 + g + 8;
    const bool va = ra < ROWS, vb = rb < ROWS;
    const float* rowa = sx + ra * XS;
    const float* rowb = sx + rb * XS;

    float d[4][4] = {};
#pragma unroll
    for (int ks = 0; ks < 16; ++ks) {
        const int k0 = ks * 8;
        uint32_t ah[4], al[4];
        {
            const float f0 = va ? rowa[k0 + t]     : 0.f;
            const float f1 = vb ? rowb[k0 + t]     : 0.f;
            const float f2 = va ? rowa[k0 + t + 4] : 0.f;
            const float f3 = vb ? rowb[k0 + t + 4] : 0.f;
            tf32_split(f0, ah[0], al[0]);
            tf32_split(f1, ah[1], al[1]);
            tf32_split(f2, ah[2], al[2]);
            tf32_split(f3, ah[3], al[3]);
        }
        const float* w0 = swb + (k0 + t) * WS + n0 + g;
        const float* w1 = swb + (k0 + t + 4) * WS + n0 + g;
#pragma unroll
        for (int ns = 0; ns < 4; ++ns) {
            uint32_t bh[2], bl[2];
            tf32_split(w0[ns * 8], bh[0], bl[0]);
            tf32_split(w1[ns * 8], bh[1], bl[1]);
            mma_tf32(d[ns], ah, bh);
            mma_tf32(d[ns], ah, bl);
            mma_tf32(d[ns], al, bh);
        }
    }
    // store with bias (+relu); c-frag: (g, 2t), (g, 2t+1), (g+8, 2t), (g+8, 2t+1)
#pragma unroll
    for (int ns = 0; ns < 4; ++ns) {
        const int c = n0 + ns * 8 + 2 * t;
        const float b0 = __ldg(&bias[c]), b1 = __ldg(&bias[c + 1]);
        float v0 = d[ns][0] + b0, v1 = d[ns][1] + b1;
        float v2 = d[ns][2] + b0, v3 = d[ns][3] + b1;
        if (RELU) {
            v0 = fmaxf(v0, 0.f); v1 = fmaxf(v1, 0.f);
            v2 = fmaxf(v2, 0.f); v3 = fmaxf(v3, 0.f);
        }
        if (va) { dst[ra * XS + c] = v0; dst[ra * XS + c + 1] = v1; }
        if (vb) { dst[rb * XS + c] = v2; dst[rb * XS + c + 1] = v3; }
    }
}

// x[r] = LN(x[r] + add[r]) * g + b
__device__ __forceinline__ void ln_add(float* __restrict__ sx,
                                       const float* __restrict__ add,
                                       const float* __restrict__ g,
                                       const float* __restrict__ b,
                                       int warp, int lane) {
    const int c = lane * 4;
    const float4 gv = *(const float4*)&g[c];
    const float4 bvec = *(const float4*)&b[c];
    for (int r = warp; r < ROWS; r += NWARPS) {
        const float4 xv = *(const float4*)&sx[r * XS + c];
        const float4 av = *(const float4*)&add[r * XS + c];
        float4 t;
        t.x = xv.x + av.x; t.y = xv.y + av.y; t.z = xv.z + av.z; t.w = xv.w + av.w;
        float s  = t.x + t.y + t.z + t.w;
        float sq = t.x * t.x + t.y * t.y + t.z * t.z + t.w * t.w;
#pragma unroll
        for (int o = 16; o; o >>= 1) {
            s  += __shfl_xor_sync(0xFFFFFFFFu, s,  o);
            sq += __shfl_xor_sync(0xFFFFFFFFu, sq, o);
        }
        const float mu  = s * (1.0f / D);
        const float var = sq * (1.0f / D) - mu * mu;
        const float inv = rsqrtf(var + EPS);
        float4 o4;
        o4.x = (t.x - mu) * inv * gv.x + bvec.x;
        o4.y = (t.y - mu) * inv * gv.y + bvec.y;
        o4.z = (t.z - mu) * inv * gv.z + bvec.z;
        o4.w = (t.w - mu) * inv * gv.w + bvec.w;
        *(float4*)&sx[r * XS + c] = o4;
    }
}

// ---------------------------------------------------------------------------
__global__ __launch_bounds__(NTHREADS, 1)
void artistbert_kernel(const float* __restrict__ X,    const float* __restrict__ mask_in,
                       const float* __restrict__ seg_in,
                       const float* __restrict__ We,   const float* __restrict__ be,
                       const float* __restrict__ Wp,   const float* __restrict__ bp,
                       const float* __restrict__ Wsg,  const float* __restrict__ bsg,
                       const float* __restrict__ g1,   const float* __restrict__ b1,
                       const float* __restrict__ Wq,   const float* __restrict__ bq,
                       const float* __restrict__ Wk,   const float* __restrict__ bk,
                       const float* __restrict__ Wv,   const float* __restrict__ bv,
                       const float* __restrict__ g2,   const float* __restrict__ b2,
                       const float* __restrict__ Wd,   const float* __restrict__ bd,
                       const float* __restrict__ Wo,   const float* __restrict__ bo,
                       float* __restrict__ out) {
    extern __shared__ float sm[];
    float* swb   = sm + OFF_WB;
    float* sx    = sm + OFF_X;
    float* sq    = sm + OFF_Q;
    float* sk    = sm + OFF_K;
    float* sv    = sm + OFF_V;
    float* ss    = sm + OFF_SC;
    float* smask = sm + OFF_M;
    float* sseg  = sm + OFF_SEG;

    const int tid  = threadIdx.x;
    const int warp = tid >> 5;
    const int lane = tid & 31;
    const int c4   = lane * 4;
    const int  b0       = blockIdx.x * BQ;
    const long base_row = (long)b0 * S;

    // ---- stage embedding tables + per-tile inputs ----
    for (int i = tid; i < V * D; i += NTHREADS) swb[i] = We[i];
    for (int i = tid; i < S * D; i += NTHREADS) {
        const int d = i & (D - 1);
        sq[i] = Wp[i] + bp[d] + be[d] + bsg[d];   // combined positional + biases
    }
    for (int i = tid; i < NSEG * D; i += NTHREADS) sq[S * D + i] = Wsg[i];
    {
        const float* Xb = X + base_row * V;
        for (int i = tid; i < ROWS * V; i += NTHREADS) sv[i] = Xb[i];
    }
    for (int i = tid; i < ROWS; i += NTHREADS) smask[i] = mask_in[base_row + i];
    {
        const float* Sg = seg_in + base_row * NSEG;
        for (int i = tid; i < ROWS * NSEG; i += NTHREADS) sseg[i] = Sg[i];
    }
    __syncthreads();

    // ---- embedding: sx = X@We + posc + seg@Wsg (fp32 SIMT) ----
    for (int r = warp; r < ROWS; r += NWARPS) {
        const int s = r % S;
        float4 acc = *(const float4*)&sq[s * D + c4];
#pragma unroll
        for (int j = 0; j < NSEG; ++j) {
            const float svv = sseg[r * NSEG + j];
            const float4 wv = *(const float4*)&sq[S * D + j * D + c4];
            FMA4(acc, svv, wv)
        }
        const float* xr = &sv[r * V];
#pragma unroll
        for (int vtok = 0; vtok < V; ++vtok) {
            const float xv = xr[vtok];
            const float4 wv = *(const float4*)&swb[vtok * D + c4];
            FMA4(acc, xv, wv)
        }
        *(float4*)&sx[r * XS + c4] = acc;
    }
    __syncthreads();

    // ---- transformer layers ----
    for (int li = 0; li < NL; ++li) {
        // q = relu(x@Wq+bq)
        load_w(Wq + li * D * D, swb, tid); __syncthreads();
        gemm_mma<true>(sx, swb, bq + li * D, sq, warp, lane); __syncthreads();
        // k = relu(x@Wk+bk)
        load_w(Wk + li * D * D, swb, tid); __syncthreads();
        gemm_mma<true>(sx, swb, bk + li * D, sk, warp, lane); __syncthreads();
        // v = relu(x@Wv+bv)
        load_w(Wv + li * D * D, swb, tid); __syncthreads();
        gemm_mma<true>(sx, swb, bv + li * D, sv, warp, lane); __syncthreads();

        // scores[b][qi][ki] = q.k (warp per dot)
        for (int idx = warp; idx < BQ * S * S; idx += NWARPS) {
            const int b   = idx / (S * S);
            const int rem = idx - b * S * S;
            const int qi  = rem / S;
            const int ki  = rem - qi * S;
            const float4 qv = *(const float4*)&sq[(b * S + qi) * XS + c4];
            const float4 kv = *(const float4*)&sk[(b * S + ki) * XS + c4];
            float p = qv.x * kv.x + qv.y * kv.y + qv.z * kv.z + qv.w * kv.w;
#pragma unroll
            for (int o = 16; o; o >>= 1) p += __shfl_xor_sync(0xFFFFFFFFu, p, o);
            if (lane == 0) ss[idx] = p;
        }
        __syncthreads();

        // softmax (thread per (b,qi) row)
        if (tid < ROWS) {
            float* row = &ss[(tid / S) * S * S + (tid % S) * S];
            float mx = row[0];
#pragma unroll
            for (int j = 1; j < S; ++j) mx = fmaxf(mx, row[j]);
            float sum = 0.f;
#pragma unroll
            for (int j = 0; j < S; ++j) { const float e = __expf(row[j] - mx); row[j] = e; sum += e; }
            const float inv = 1.0f / sum;
#pragma unroll
            for (int j = 0; j < S; ++j) row[j] *= inv;
        }
        __syncthreads();

        // attn = (scores @ v) * mask -> sq (q consumed)
        for (int r = warp; r < ROWS; r += NWARPS) {
            const int b  = r / S;
            const int qi = r - b * S;
            const float* p  = &ss[b * S * S + qi * S];
            const float* vb = &sv[(b * S) * XS];
            float4 acc = make_float4(0.f, 0.f, 0.f, 0.f);
#pragma unroll
            for (int ki = 0; ki < S; ++ki) {
                const float pv = p[ki];
                const float4 vv = *(const float4*)&vb[ki * XS + c4];
                FMA4(acc, pv, vv)
            }
            const float m = smask[r];
            acc.x *= m; acc.y *= m; acc.z *= m; acc.w *= m;
            *(float4*)&sq[r * XS + c4] = acc;
        }
        __syncthreads();

        // x = LN(x + attn)
        ln_add(sx, sq, g1 + li * D, b1 + li * D, warp, lane);
        __syncthreads();

        // d = x@Wd + bd
        load_w(Wd + li * D * D, swb, tid); __syncthreads();
        gemm_mma<false>(sx, swb, bd + li * D, sq, warp, lane); __syncthreads();

        // x = LN(x + d)
        ln_add(sx, sq, g2 + li * D, b2 + li * D, warp, lane);
        __syncthreads();
    }

    // ---- output projection: out = x@Wo + bo (fp32 SIMT) ----
    for (int i = tid; i < D * 32; i += NTHREADS) {
        const int k = i >> 5, n = i & 31;
        swb[i] = (n < V) ? Wo[k * V + n] : 0.f;
    }
    __syncthreads();
    for (int r = warp; r < ROWS; r += NWARPS) {
        if (lane < V) {
            float acc = bo[lane];
            const float* xr = &sx[r * XS];
#pragma unroll 8
            for (int k = 0; k < D; ++k) acc += xr[k] * swb[k * 32 + lane];
            out[(base_row + r) * V + lane] = acc;
        }
    }
}

// ---------------------------------------------------------------------------
extern "C" void kernel_launch(void* const* d_in, const int* in_sizes, int n_in,
                              void* d_out, int out_size) {
    (void)in_sizes; (void)n_in; (void)out_size;
    const float* X    = (const float*)d_in[0];
    const float* mask = (const float*)d_in[1];
    const float* seg  = (const float*)d_in[2];
    const float* We   = (const float*)d_in[3];
    const float* be   = (const float*)d_in[4];
    const float* Wp   = (const float*)d_in[5];
    const float* bp   = (const float*)d_in[6];
    const float* Wsg  = (const float*)d_in[7];
    const float* bsg  = (const float*)d_in[8];
    const float* g1   = (const float*)d_in[9];
    const float* b1   = (const float*)d_in[10];
    const float* Wq   = (const float*)d_in[11];
    const float* bq   = (const float*)d_in[12];
    const float* Wk   = (const float*)d_in[13];
    const float* bk   = (const float*)d_in[14];
    const float* Wv   = (const float*)d_in[15];
    const float* bv   = (const float*)d_in[16];
    const float* g2   = (const float*)d_in[17];
    const float* b2   = (const float*)d_in[18];
    const float* Wd   = (const float*)d_in[19];
    const float* bd   = (const float*)d_in[20];
    const float* Wo   = (const float*)d_in[21];
    const float* bo   = (const float*)d_in[22];
    float* out = (float*)d_out;

    cudaFuncSetAttribute(artistbert_kernel,
                         cudaFuncAttributeMaxDynamicSharedMemorySize, SMEM_BYTES);
    artistbert_kernel<<<BB / BQ, NTHREADS, SMEM_BYTES>>>(
        X, mask, seg, We, be, Wp, bp, Wsg, bsg, g1, b1,
        Wq, bq, Wk, bk, Wv, bv, g2, b2, Wd, bd, Wo, bo, out);
}

// round 8
// speedup vs baseline: 1.4821x; 1.4086x over previous
#include <cuda_runtime.h>
#include <cstdint>

// Problem constants
#define BB   16384
#define S    17
#define V    29
#define D    128
#define NSEG 4
#define NL   6
#define EPS  1e-5f

// Tiling
#define BQ       4
#define ROWS     (BQ * S)       // 68
#define NTHREADS 640            // 20 warps = 5 Mtiles x 4 Ngroups
#define NWARPS   20
#define XW       68             // xh/xl row stride in words (68%32==4 -> conflict-free)
#define WW       68             // wh/wl col stride in words

// Shared memory layout (float/word offsets)
#define OFF_SX  0                        // x residual  [68][128] fp32
#define OFF_SA  8704                     // scratch A   [68][128] fp32
#define OFF_SB  17408                    // scratch B   [68][128] fp32
#define OFF_XH  26112                    // x hi  [80][XW] bf16x2 words (rows 68-79 zero pad)
#define OFF_XL  31552                    // x lo
#define OFF_WH  36992                    // W hi  [128][WW] bf16x2 words (transposed, k-pairs)
#define OFF_WL  45696                    // W lo
#define OFF_SC  54400                    // scores [4][17][17]
#define OFF_M   55556                    // mask [68]
#define OFF_SEG 55624                    // seg one-hot [68][4]
#define SMEM_FLOATS 55896
#define SMEM_BYTES  (SMEM_FLOATS * 4)    // 223,584 B (< 227KB cap)

#define FMA4(_acc_, _s_, _w_)                                                  \
    _acc_.x += (_s_) * (_w_).x; _acc_.y += (_s_) * (_w_).y;                    \
    _acc_.z += (_s_) * (_w_).z; _acc_.w += (_s_) * (_w_).w;

// ---------------------------------------------------------------------------
// bf16 helpers
// ---------------------------------------------------------------------------
// pack(lo_k, hi_k): low 16 bits = lower-k element (mma convention)
__device__ __forceinline__ uint32_t bf16x2_pack(float lo_k, float hi_k) {
    uint32_t r;
    asm("cvt.rn.bf16x2.f32 %0, %1, %2;" : "=r"(r) : "f"(hi_k), "f"(lo_k));
    return r;
}

__device__ __forceinline__ void mma_bf16(float* d, const uint32_t* a, const uint32_t* b) {
    asm volatile(
        "mma.sync.aligned.m16n8k16.row.col.f32.bf16.bf16.f32 "
        "{%0,%1,%2,%3}, {%4,%5,%6,%7}, {%8,%9}, {%0,%1,%2,%3};"
        : "+f"(d[0]), "+f"(d[1]), "+f"(d[2]), "+f"(d[3])
        : "r"(a[0]), "r"(a[1]), "r"(a[2]), "r"(a[3]), "r"(b[0]), "r"(b[1]));
}

// Split sx (fp32 [68][128]) -> xh/xl bf16x2 word arrays [r][XW].
__device__ __forceinline__ void split_x(const float* __restrict__ sx,
                                        uint32_t* __restrict__ xh,
                                        uint32_t* __restrict__ xl, int tid) {
    for (int i = tid; i < ROWS * 64; i += NTHREADS) {
        const int r = i >> 6, j = i & 63;
        const float2 f = *(const float2*)&sx[r * D + j * 2];
        const uint32_t h = bf16x2_pack(f.x, f.y);
        const float h0 = __uint_as_float(h << 16);
        const float h1 = __uint_as_float(h & 0xFFFF0000u);
        const uint32_t l = bf16x2_pack(f.x - h0, f.y - h1);
        xh[r * XW + j] = h;
        xl[r * XW + j] = l;
    }
}

// Stage W (fp32 row-major [k][n]) -> wh/wl transposed k-pair-packed bf16x2.
__device__ __forceinline__ void stage_w(const float* __restrict__ gW,
                                        uint32_t* __restrict__ wh,
                                        uint32_t* __restrict__ wl, int tid) {
    for (int i = tid; i < 64 * D; i += NTHREADS) {
        const int j = i >> 7, n = i & 127;       // kpair j, output col n
        const float w0 = __ldg(&gW[(2 * j) * D + n]);
        const float w1 = __ldg(&gW[(2 * j + 1) * D + n]);
        const uint32_t h = bf16x2_pack(w0, w1);
        const float h0 = __uint_as_float(h << 16);
        const float h1 = __uint_as_float(h & 0xFFFF0000u);
        const uint32_t l = bf16x2_pack(w0 - h0, w1 - h1);
        wh[n * WW + j] = h;
        wl[n * WW + j] = l;
    }
}

// dst[r][n] = (relu?) x[r][:] . W[:][n] + bias[n]  via bf16 3-pass mma.
template <bool RELU>
__device__ __forceinline__ void gemm_mma(const uint32_t* __restrict__ xh,
                                         const uint32_t* __restrict__ xl,
                                         const uint32_t* __restrict__ wh,
                                         const uint32_t* __restrict__ wl,
                                         const float* __restrict__ bias,
                                         float* __restrict__ dst,
                                         int warp, int lane) {
    const int mt = warp >> 2, ng = warp & 3;
    const int g = lane >> 2, t = lane & 3;
    const int r0 = mt * 16, n0 = ng * 32;
    const uint32_t* xa = xh + (r0 + g) * XW + t;
    const uint32_t* xb = xh + (r0 + g + 8) * XW + t;
    const uint32_t* ya = xl + (r0 + g) * XW + t;
    const uint32_t* yb = xl + (r0 + g + 8) * XW + t;

    float d[4][4] = {};
#pragma unroll
    for (int ks = 0; ks < 8; ++ks) {
        const int kb = ks * 8;
        uint32_t ah[4], al[4];
        ah[0] = xa[kb]; ah[1] = xb[kb]; ah[2] = xa[kb + 4]; ah[3] = xb[kb + 4];
        al[0] = ya[kb]; al[1] = yb[kb]; al[2] = ya[kb + 4]; al[3] = yb[kb + 4];
#pragma unroll
        for (int ns = 0; ns < 4; ++ns) {
            const int cw = (n0 + ns * 8 + g) * WW + kb;
            uint32_t bh[2], bl[2];
            bh[0] = wh[cw + t]; bh[1] = wh[cw + t + 4];
            bl[0] = wl[cw + t]; bl[1] = wl[cw + t + 4];
            mma_bf16(d[ns], ah, bh);
            mma_bf16(d[ns], ah, bl);
            mma_bf16(d[ns], al, bh);
        }
    }
    const int ra = r0 + g, rb = r0 + g + 8;
    const bool va = ra < ROWS, vb = rb < ROWS;
#pragma unroll
    for (int ns = 0; ns < 4; ++ns) {
        const int c = n0 + ns * 8 + 2 * t;
        const float b0 = __ldg(&bias[c]), b1 = __ldg(&bias[c + 1]);
        float v0 = d[ns][0] + b0, v1 = d[ns][1] + b1;
        float v2 = d[ns][2] + b0, v3 = d[ns][3] + b1;
        if (RELU) {
            v0 = fmaxf(v0, 0.f); v1 = fmaxf(v1, 0.f);
            v2 = fmaxf(v2, 0.f); v3 = fmaxf(v3, 0.f);
        }
        if (va) { dst[ra * D + c] = v0; dst[ra * D + c + 1] = v1; }
        if (vb) { dst[rb * D + c] = v2; dst[rb * D + c + 1] = v3; }
    }
}

// x[r] = LN(x[r] + add[r]) * g + b
__device__ __forceinline__ void ln_add(float* __restrict__ sx,
                                       const float* __restrict__ add,
                                       const float* __restrict__ g,
                                       const float* __restrict__ b,
                                       int warp, int lane) {
    const int c = lane * 4;
    const float4 gv = *(const float4*)&g[c];
    const float4 bvec = *(const float4*)&b[c];
    for (int r = warp; r < ROWS; r += NWARPS) {
        const float4 xv = *(const float4*)&sx[r * D + c];
        const float4 av = *(const float4*)&add[r * D + c];
        float4 t;
        t.x = xv.x + av.x; t.y = xv.y + av.y; t.z = xv.z + av.z; t.w = xv.w + av.w;
        float s  = t.x + t.y + t.z + t.w;
        float sq = t.x * t.x + t.y * t.y + t.z * t.z + t.w * t.w;
#pragma unroll
        for (int o = 16; o; o >>= 1) {
            s  += __shfl_xor_sync(0xFFFFFFFFu, s,  o);
            sq += __shfl_xor_sync(0xFFFFFFFFu, sq, o);
        }
        const float mu  = s * (1.0f / D);
        const float var = sq * (1.0f / D) - mu * mu;
        const float inv = rsqrtf(var + EPS);
        float4 o4;
        o4.x = (t.x - mu) * inv * gv.x + bvec.x;
        o4.y = (t.y - mu) * inv * gv.y + bvec.y;
        o4.z = (t.z - mu) * inv * gv.z + bvec.z;
        o4.w = (t.w - mu) * inv * gv.w + bvec.w;
        *(float4*)&sx[r * D + c] = o4;
    }
}

// ---------------------------------------------------------------------------
__global__ __launch_bounds__(NTHREADS, 1)
void artistbert_kernel(const float* __restrict__ X,    const float* __restrict__ mask_in,
                       const float* __restrict__ seg_in,
                       const float* __restrict__ We,   const float* __restrict__ be,
                       const float* __restrict__ Wp,   const float* __restrict__ bp,
                       const float* __restrict__ Wsg,  const float* __restrict__ bsg,
                       const float* __restrict__ g1,   const float* __restrict__ b1,
                       const float* __restrict__ Wq,   const float* __restrict__ bq,
                       const float* __restrict__ Wk,   const float* __restrict__ bk,
                       const float* __restrict__ Wv,   const float* __restrict__ bv,
                       const float* __restrict__ g2,   const float* __restrict__ b2,
                       const float* __restrict__ Wd,   const float* __restrict__ bd,
                       const float* __restrict__ Wo,   const float* __restrict__ bo,
                       float* __restrict__ out) {
    extern __shared__ float sm[];
    float*    sx    = sm + OFF_SX;
    float*    sa    = sm + OFF_SA;
    float*    sb    = sm + OFF_SB;
    uint32_t* xh    = (uint32_t*)(sm + OFF_XH);
    uint32_t* xl    = (uint32_t*)(sm + OFF_XL);
    uint32_t* wh    = (uint32_t*)(sm + OFF_WH);
    uint32_t* wl    = (uint32_t*)(sm + OFF_WL);
    float*    ss    = sm + OFF_SC;
    float*    smask = sm + OFF_M;
    float*    sseg  = sm + OFF_SEG;

    const int tid  = threadIdx.x;
    const int warp = tid >> 5;
    const int lane = tid & 31;
    const int c4   = lane * 4;
    const int  b0       = blockIdx.x * BQ;
    const long base_row = (long)b0 * S;

    // zero xh/xl (incl. pad rows 68-79; live rows get overwritten by split_x)
    for (int i = tid; i < 80 * XW; i += NTHREADS) { xh[i] = 0u; xl[i] = 0u; }

    // ---- stage embedding tables + per-tile inputs ----
    float* swb = sm + OFF_WH;                      // reuse W region for We
    for (int i = tid; i < V * D; i += NTHREADS) swb[i] = We[i];
    for (int i = tid; i < S * D; i += NTHREADS) {
        const int d = i & (D - 1);
        sa[i] = Wp[i] + bp[d] + be[d] + bsg[d];    // combined positional + biases
    }
    for (int i = tid; i < NSEG * D; i += NTHREADS) sa[S * D + i] = Wsg[i];
    {
        const float* Xb = X + base_row * V;
        for (int i = tid; i < ROWS * V; i += NTHREADS) sb[i] = Xb[i];
    }
    for (int i = tid; i < ROWS; i += NTHREADS) smask[i] = mask_in[base_row + i];
    {
        const float* Sg = seg_in + base_row * NSEG;
        for (int i = tid; i < ROWS * NSEG; i += NTHREADS) sseg[i] = Sg[i];
    }
    __syncthreads();

    // ---- embedding: sx = X@We + posc + seg@Wsg (fp32 SIMT) ----
    for (int r = warp; r < ROWS; r += NWARPS) {
        const int s = r % S;
        float4 acc = *(const float4*)&sa[s * D + c4];
#pragma unroll
        for (int j = 0; j < NSEG; ++j) {
            const float svv = sseg[r * NSEG + j];
            const float4 wv = *(const float4*)&sa[S * D + j * D + c4];
            FMA4(acc, svv, wv)
        }
        const float* xr = &sb[r * V];
#pragma unroll
        for (int vtok = 0; vtok < V; ++vtok) {
            const float xv = xr[vtok];
            const float4 wv = *(const float4*)&swb[vtok * D + c4];
            FMA4(acc, xv, wv)
        }
        *(float4*)&sx[r * D + c4] = acc;
    }
    __syncthreads();

    // ---- transformer layers ----
    for (int li = 0; li < NL; ++li) {
        // split x + stage Wq (same region)
        split_x(sx, xh, xl, tid);
        stage_w(Wq + li * D * D, wh, wl, tid);
        __syncthreads();

        gemm_mma<true>(xh, xl, wh, wl, bq + li * D, sa, warp, lane);   // q -> sa
        __syncthreads();

        stage_w(Wk + li * D * D, wh, wl, tid);
        __syncthreads();

        gemm_mma<true>(xh, xl, wh, wl, bk + li * D, sb, warp, lane);   // k -> sb
        __syncthreads();

        // scores (q.k) + stage Wv (same region)
        for (int idx = warp; idx < BQ * S * S; idx += NWARPS) {
            const int b   = idx / (S * S);
            const int rem = idx - b * S * S;
            const int qi  = rem / S;
            const int ki  = rem - qi * S;
            const float4 qv = *(const float4*)&sa[(b * S + qi) * D + c4];
            const float4 kv = *(const float4*)&sb[(b * S + ki) * D + c4];
            float p = qv.x * kv.x + qv.y * kv.y + qv.z * kv.z + qv.w * kv.w;
#pragma unroll
            for (int o = 16; o; o >>= 1) p += __shfl_xor_sync(0xFFFFFFFFu, p, o);
            if (lane == 0) ss[idx] = p;
        }
        stage_w(Wv + li * D * D, wh, wl, tid);
        __syncthreads();

        // softmax (thread per (b,qi) row)
        if (tid < ROWS) {
            float* row = &ss[(tid / S) * S * S + (tid % S) * S];
            float mx = row[0];
#pragma unroll
            for (int j = 1; j < S; ++j) mx = fmaxf(mx, row[j]);
            float sum = 0.f;
#pragma unroll
            for (int j = 0; j < S; ++j) { const float e = __expf(row[j] - mx); row[j] = e; sum += e; }
            const float inv = 1.0f / sum;
#pragma unroll
            for (int j = 0; j < S; ++j) row[j] *= inv;
        }
        __syncthreads();

        gemm_mma<true>(xh, xl, wh, wl, bv + li * D, sa, warp, lane);   // v -> sa (q dead)
        __syncthreads();

        // attn = (scores @ v) * mask -> sb (k dead)
        for (int r = warp; r < ROWS; r += NWARPS) {
            const int b  = r / S;
            const int qi = r - b * S;
            const float* p  = &ss[b * S * S + qi * S];
            const float* vb = &sa[(b * S) * D];
            float4 acc = make_float4(0.f, 0.f, 0.f, 0.f);
#pragma unroll
            for (int ki = 0; ki < S; ++ki) {
                const float pv = p[ki];
                const float4 vv = *(const float4*)&vb[ki * D + c4];
                FMA4(acc, pv, vv)
            }
            const float m = smask[r];
            acc.x *= m; acc.y *= m; acc.z *= m; acc.w *= m;
            *(float4*)&sb[r * D + c4] = acc;
        }
        __syncthreads();

        // x = LN(x + attn)
        ln_add(sx, sb, g1 + li * D, b1 + li * D, warp, lane);
        __syncthreads();

        // split x' + stage Wd
        split_x(sx, xh, xl, tid);
        stage_w(Wd + li * D * D, wh, wl, tid);
        __syncthreads();

        gemm_mma<false>(xh, xl, wh, wl, bd + li * D, sa, warp, lane);  // d -> sa
        __syncthreads();

        // x = LN(x + d)
        ln_add(sx, sa, g2 + li * D, b2 + li * D, warp, lane);
        __syncthreads();
    }

    // ---- output projection: out = x@Wo + bo (fp32 SIMT) ----
    for (int i = tid; i < D * 32; i += NTHREADS) {
        const int k = i >> 5, n = i & 31;
        swb[i] = (n < V) ? Wo[k * V + n] : 0.f;
    }
    __syncthreads();
    for (int r = warp; r < ROWS; r += NWARPS) {
        if (lane < V) {
            float acc = bo[lane];
            const float* xr = &sx[r * D];
#pragma unroll 8
            for (int k = 0; k < D; ++k) acc += xr[k] * swb[k * 32 + lane];
            out[(base_row + r) * V + lane] = acc;
        }
    }
}

// ---------------------------------------------------------------------------
extern "C" void kernel_launch(void* const* d_in, const int* in_sizes, int n_in,
                              void* d_out, int out_size) {
    (void)in_sizes; (void)n_in; (void)out_size;
    const float* X    = (const float*)d_in[0];
    const float* mask = (const float*)d_in[1];
    const float* seg  = (const float*)d_in[2];
    const float* We   = (const float*)d_in[3];
    const float* be   = (const float*)d_in[4];
    const float* Wp   = (const float*)d_in[5];
    const float* bp   = (const float*)d_in[6];
    const float* Wsg  = (const float*)d_in[7];
    const float* bsg  = (const float*)d_in[8];
    const float* g1   = (const float*)d_in[9];
    const float* b1   = (const float*)d_in[10];
    const float* Wq   = (const float*)d_in[11];
    const float* bq   = (const float*)d_in[12];
    const float* Wk   = (const float*)d_in[13];
    const float* bk   = (const float*)d_in[14];
    const float* Wv   = (const float*)d_in[15];
    const float* bv   = (const float*)d_in[16];
    const float* g2   = (const float*)d_in[17];
    const float* b2   = (const float*)d_in[18];
    const float* Wd   = (const float*)d_in[19];
    const float* bd   = (const float*)d_in[20];
    const float* Wo   = (const float*)d_in[21];
    const float* bo   = (const float*)d_in[22];
    float* out = (float*)d_out;

    cudaFuncSetAttribute(artistbert_kernel,
                         cudaFuncAttributeMaxDynamicSharedMemorySize, SMEM_BYTES);
    artistbert_kernel<<<BB / BQ, NTHREADS, SMEM_BYTES>>>(
        X, mask, seg, We, be, Wp, bp, Wsg, bsg, g1, b1,
        Wq, bq, Wk, bk, Wv, bv, g2, b2, Wd, bd, Wo, bo, out);
}

// round 9
// speedup vs baseline: 1.6605x; 1.1204x over previous
#include <cuda_runtime.h>
#include <cstdint>

// Problem constants
#define BB   16384
#define S    17
#define V    29
#define D    128
#define NSEG 4
#define NL   6
#define EPS  1e-5f

// Tiling
#define BQ       4
#define ROWS     (BQ * S)       // 68
#define NTHREADS 640            // 20 warps = 5 Mtiles x 4 Ngroups (GEMM), 4 batches x 5 subs (attn)
#define NWARPS   20
#define XW       68             // xh/xl row stride in words (68%32==4 -> conflict-free)
#define WW       68             // wh/wl col stride in words

// Shared memory layout (float/word offsets)
#define OFF_SX  0                        // x residual  [68][128] fp32
#define OFF_SA  8704                     // scratch A   [68][128] fp32
#define OFF_SB  17408                    // scratch B   [68][128] fp32
#define OFF_XH  26112                    // x hi  [80][XW] bf16x2 words (rows 68-79 zero pad)
#define OFF_XL  31552                    // x lo
#define OFF_WH  36992                    // W hi  [128][WW] bf16x2 words (transposed, k-pairs)
#define OFF_WL  45696                    // W lo
#define OFF_SC  54400                    // scores [4][17][17]
#define OFF_M   55556                    // mask [68]
#define OFF_SEG 55624                    // seg one-hot [68][4]
#define SMEM_FLOATS 55896
#define SMEM_BYTES  (SMEM_FLOATS * 4)    // 223,584 B

#define FMA4(_acc_, _s_, _w_)                                                  \
    _acc_.x += (_s_) * (_w_).x; _acc_.y += (_s_) * (_w_).y;                    \
    _acc_.z += (_s_) * (_w_).z; _acc_.w += (_s_) * (_w_).w;

// ---------------------------------------------------------------------------
// bf16 helpers
// ---------------------------------------------------------------------------
// pack(lo_k, hi_k): low 16 bits = lower-k element (mma convention)
__device__ __forceinline__ uint32_t bf16x2_pack(float lo_k, float hi_k) {
    uint32_t r;
    asm("cvt.rn.bf16x2.f32 %0, %1, %2;" : "=r"(r) : "f"(hi_k), "f"(lo_k));
    return r;
}

__device__ __forceinline__ void mma_bf16(float* d, const uint32_t* a, const uint32_t* b) {
    asm volatile(
        "mma.sync.aligned.m16n8k16.row.col.f32.bf16.bf16.f32 "
        "{%0,%1,%2,%3}, {%4,%5,%6,%7}, {%8,%9}, {%0,%1,%2,%3};"
        : "+f"(d[0]), "+f"(d[1]), "+f"(d[2]), "+f"(d[3])
        : "r"(a[0]), "r"(a[1]), "r"(a[2]), "r"(a[3]), "r"(b[0]), "r"(b[1]));
}

// Split a float4 (cols c..c+3) into two bf16x2 hi words + two lo words and
// store at word index r*XW + (c>>1).
__device__ __forceinline__ void store_split4(uint32_t* __restrict__ xh,
                                             uint32_t* __restrict__ xl,
                                             int r, int c, float4 o4) {
    const uint32_t h0 = bf16x2_pack(o4.x, o4.y);
    const uint32_t h1 = bf16x2_pack(o4.z, o4.w);
    const float a0 = __uint_as_float(h0 << 16);
    const float a1 = __uint_as_float(h0 & 0xFFFF0000u);
    const float a2 = __uint_as_float(h1 << 16);
    const float a3 = __uint_as_float(h1 & 0xFFFF0000u);
    const uint32_t l0 = bf16x2_pack(o4.x - a0, o4.y - a1);
    const uint32_t l1 = bf16x2_pack(o4.z - a2, o4.w - a3);
    uint2 hh; hh.x = h0; hh.y = h1;
    uint2 ll; ll.x = l0; ll.y = l1;
    *(uint2*)&xh[r * XW + (c >> 1)] = hh;
    *(uint2*)&xl[r * XW + (c >> 1)] = ll;
}

// Stage W (fp32 row-major [k][n]) -> wh/wl transposed k-pair-packed bf16x2.
__device__ __forceinline__ void stage_w(const float* __restrict__ gW,
                                        uint32_t* __restrict__ wh,
                                        uint32_t* __restrict__ wl, int tid) {
    for (int i = tid; i < 64 * D; i += NTHREADS) {
        const int j = i >> 7, n = i & 127;       // kpair j, output col n
        const float w0 = __ldg(&gW[(2 * j) * D + n]);
        const float w1 = __ldg(&gW[(2 * j + 1) * D + n]);
        const uint32_t h = bf16x2_pack(w0, w1);
        const float h0 = __uint_as_float(h << 16);
        const float h1 = __uint_as_float(h & 0xFFFF0000u);
        const uint32_t l = bf16x2_pack(w0 - h0, w1 - h1);
        wh[n * WW + j] = h;
        wl[n * WW + j] = l;
    }
}

// dst[r][n] = (relu?) x[r][:] . W[:][n] + bias[n]  via bf16 3-pass mma.
template <bool RELU>
__device__ __forceinline__ void gemm_mma(const uint32_t* __restrict__ xh,
                                         const uint32_t* __restrict__ xl,
                                         const uint32_t* __restrict__ wh,
                                         const uint32_t* __restrict__ wl,
                                         const float* __restrict__ bias,
                                         float* __restrict__ dst,
                                         int warp, int lane) {
    const int mt = warp >> 2, ng = warp & 3;
    const int g = lane >> 2, t = lane & 3;
    const int r0 = mt * 16, n0 = ng * 32;
    const uint32_t* xa = xh + (r0 + g) * XW + t;
    const uint32_t* xb = xh + (r0 + g + 8) * XW + t;
    const uint32_t* ya = xl + (r0 + g) * XW + t;
    const uint32_t* yb = xl + (r0 + g + 8) * XW + t;

    float d[4][4] = {};
#pragma unroll
    for (int ks = 0; ks < 8; ++ks) {
        const int kb = ks * 8;
        uint32_t ah[4], al[4];
        ah[0] = xa[kb]; ah[1] = xb[kb]; ah[2] = xa[kb + 4]; ah[3] = xb[kb + 4];
        al[0] = ya[kb]; al[1] = yb[kb]; al[2] = ya[kb + 4]; al[3] = yb[kb + 4];
#pragma unroll
        for (int ns = 0; ns < 4; ++ns) {
            const int cw = (n0 + ns * 8 + g) * WW + kb;
            uint32_t bh[2], bl[2];
            bh[0] = wh[cw + t]; bh[1] = wh[cw + t + 4];
            bl[0] = wl[cw + t]; bl[1] = wl[cw + t + 4];
            mma_bf16(d[ns], ah, bh);
            mma_bf16(d[ns], ah, bl);
            mma_bf16(d[ns], al, bh);
        }
    }
    const int ra = r0 + g, rb = r0 + g + 8;
    const bool va = ra < ROWS, vb = rb < ROWS;
#pragma unroll
    for (int ns = 0; ns < 4; ++ns) {
        const int c = n0 + ns * 8 + 2 * t;
        const float b0 = __ldg(&bias[c]), b1 = __ldg(&bias[c + 1]);
        float v0 = d[ns][0] + b0, v1 = d[ns][1] + b1;
        float v2 = d[ns][2] + b0, v3 = d[ns][3] + b1;
        if (RELU) {
            v0 = fmaxf(v0, 0.f); v1 = fmaxf(v1, 0.f);
            v2 = fmaxf(v2, 0.f); v3 = fmaxf(v3, 0.f);
        }
        if (va) { dst[ra * D + c] = v0; dst[ra * D + c + 1] = v1; }
        if (vb) { dst[rb * D + c] = v2; dst[rb * D + c + 1] = v3; }
    }
}

// x[r] = LN(x[r] + add[r]) * g + b, ALSO writes the bf16 hi/lo split of the
// new x (fused: values are already in registers).
__device__ __forceinline__ void ln_add_split(float* __restrict__ sx,
                                             const float* __restrict__ add,
                                             const float* __restrict__ g,
                                             const float* __restrict__ b,
                                             uint32_t* __restrict__ xh,
                                             uint32_t* __restrict__ xl,
                                             int warp, int lane) {
    const int c = lane * 4;
    const float4 gv = *(const float4*)&g[c];
    const float4 bvec = *(const float4*)&b[c];
    for (int r = warp; r < ROWS; r += NWARPS) {
        const float4 xv = *(const float4*)&sx[r * D + c];
        const float4 av = *(const float4*)&add[r * D + c];
        float4 t;
        t.x = xv.x + av.x; t.y = xv.y + av.y; t.z = xv.z + av.z; t.w = xv.w + av.w;
        float s  = t.x + t.y + t.z + t.w;
        float sq = t.x * t.x + t.y * t.y + t.z * t.z + t.w * t.w;
#pragma unroll
        for (int o = 16; o; o >>= 1) {
            s  += __shfl_xor_sync(0xFFFFFFFFu, s,  o);
            sq += __shfl_xor_sync(0xFFFFFFFFu, sq, o);
        }
        const float mu  = s * (1.0f / D);
        const float var = sq * (1.0f / D) - mu * mu;
        const float inv = rsqrtf(var + EPS);
        float4 o4;
        o4.x = (t.x - mu) * inv * gv.x + bvec.x;
        o4.y = (t.y - mu) * inv * gv.y + bvec.y;
        o4.z = (t.z - mu) * inv * gv.z + bvec.z;
        o4.w = (t.w - mu) * inv * gv.w + bvec.w;
        *(float4*)&sx[r * D + c] = o4;
        store_split4(xh, xl, r, c, o4);
    }
}

// ---------------------------------------------------------------------------
__global__ __launch_bounds__(NTHREADS, 1)
void artistbert_kernel(const float* __restrict__ X,    const float* __restrict__ mask_in,
                       const float* __restrict__ seg_in,
                       const float* __restrict__ We,   const float* __restrict__ be,
                       const float* __restrict__ Wp,   const float* __restrict__ bp,
                       const float* __restrict__ Wsg,  const float* __restrict__ bsg,
                       const float* __restrict__ g1,   const float* __restrict__ b1,
                       const float* __restrict__ Wq,   const float* __restrict__ bq,
                       const float* __restrict__ Wk,   const float* __restrict__ bk,
                       const float* __restrict__ Wv,   const float* __restrict__ bv,
                       const float* __restrict__ g2,   const float* __restrict__ b2,
                       const float* __restrict__ Wd,   const float* __restrict__ bd,
                       const float* __restrict__ Wo,   const float* __restrict__ bo,
                       float* __restrict__ out) {
    extern __shared__ float sm[];
    float*    sx    = sm + OFF_SX;
    float*    sa    = sm + OFF_SA;
    float*    sb    = sm + OFF_SB;
    uint32_t* xh    = (uint32_t*)(sm + OFF_XH);
    uint32_t* xl    = (uint32_t*)(sm + OFF_XL);
    uint32_t* wh    = (uint32_t*)(sm + OFF_WH);
    uint32_t* wl    = (uint32_t*)(sm + OFF_WL);
    float*    ss    = sm + OFF_SC;
    float*    smask = sm + OFF_M;
    float*    sseg  = sm + OFF_SEG;

    const int tid  = threadIdx.x;
    const int warp = tid >> 5;
    const int lane = tid & 31;
    const int c4   = lane * 4;
    const int wb   = warp / 5;          // batch for scores/attn tiling (0..3)
    const int wsub = warp - wb * 5;     // sub-warp (0..4)
    const int  b0       = blockIdx.x * BQ;
    const long base_row = (long)b0 * S;

    // zero xh/xl (incl. pad rows 68-79; live rows get overwritten)
    for (int i = tid; i < 80 * XW; i += NTHREADS) { xh[i] = 0u; xl[i] = 0u; }

    // ---- stage embedding tables + per-tile inputs ----
    float* swb = sm + OFF_WH;                      // reuse W region for We
    for (int i = tid; i < V * D; i += NTHREADS) swb[i] = We[i];
    for (int i = tid; i < S * D; i += NTHREADS) {
        const int d = i & (D - 1);
        sa[i] = Wp[i] + bp[d] + be[d] + bsg[d];    // combined positional + biases
    }
    for (int i = tid; i < NSEG * D; i += NTHREADS) sa[S * D + i] = Wsg[i];
    {
        const float* Xb = X + base_row * V;
        for (int i = tid; i < ROWS * V; i += NTHREADS) sb[i] = Xb[i];
    }
    for (int i = tid; i < ROWS; i += NTHREADS) smask[i] = mask_in[base_row + i];
    {
        const float* Sg = seg_in + base_row * NSEG;
        for (int i = tid; i < ROWS * NSEG; i += NTHREADS) sseg[i] = Sg[i];
    }
    __syncthreads();

    // ---- embedding: sx = X@We + posc + seg@Wsg (fp32 SIMT) + fused split ----
    for (int r = warp; r < ROWS; r += NWARPS) {
        const int s = r % S;
        float4 acc = *(const float4*)&sa[s * D + c4];
#pragma unroll
        for (int j = 0; j < NSEG; ++j) {
            const float svv = sseg[r * NSEG + j];
            const float4 wv = *(const float4*)&sa[S * D + j * D + c4];
            FMA4(acc, svv, wv)
        }
        const float* xr = &sb[r * V];
#pragma unroll
        for (int vtok = 0; vtok < V; ++vtok) {
            const float xv = xr[vtok];
            const float4 wv = *(const float4*)&swb[vtok * D + c4];
            FMA4(acc, xv, wv)
        }
        *(float4*)&sx[r * D + c4] = acc;
        store_split4(xh, xl, r, c4, acc);
    }
    __syncthreads();

    // ---- transformer layers ----
    for (int li = 0; li < NL; ++li) {
        // stage Wq (x splits already available from prev epilogue)
        stage_w(Wq + li * D * D, wh, wl, tid);
        __syncthreads();

        gemm_mma<true>(xh, xl, wh, wl, bq + li * D, sa, warp, lane);   // q -> sa
        __syncthreads();

        stage_w(Wk + li * D * D, wh, wl, tid);
        __syncthreads();

        gemm_mma<true>(xh, xl, wh, wl, bk + li * D, sb, warp, lane);   // k -> sb
        __syncthreads();

        // ---- tiled scores: warp (wb, wsub) handles q-rows {wsub+5t} of batch wb.
        // q rows held in registers; each k row streamed ONCE per warp.
        {
            float4 qf[4];
#pragma unroll
            for (int t = 0; t < 4; ++t) {
                const int row = wsub + 5 * t;
                qf[t] = (row < S) ? *(const float4*)&sa[(wb * S + row) * D + c4]
                                  : make_float4(0.f, 0.f, 0.f, 0.f);
            }
            for (int ki = 0; ki < S; ++ki) {
                const float4 kv = *(const float4*)&sb[(wb * S + ki) * D + c4];
#pragma unroll
                for (int t = 0; t < 4; ++t) {
                    const int row = wsub + 5 * t;
                    if (row < S) {
                        float p = qf[t].x * kv.x + qf[t].y * kv.y
                                + qf[t].z * kv.z + qf[t].w * kv.w;
#pragma unroll
                        for (int o = 16; o; o >>= 1) p += __shfl_xor_sync(0xFFFFFFFFu, p, o);
                        if (lane == 0) ss[wb * S * S + row * S + ki] = p;
                    }
                }
            }
        }
        stage_w(Wv + li * D * D, wh, wl, tid);
        __syncthreads();

        // softmax (thread per (b,qi) row)
        if (tid < ROWS) {
            float* row = &ss[(tid / S) * S * S + (tid % S) * S];
            float mx = row[0];
#pragma unroll
            for (int j = 1; j < S; ++j) mx = fmaxf(mx, row[j]);
            float sum = 0.f;
#pragma unroll
            for (int j = 0; j < S; ++j) { const float e = __expf(row[j] - mx); row[j] = e; sum += e; }
            const float inv = 1.0f / sum;
#pragma unroll
            for (int j = 0; j < S; ++j) row[j] *= inv;
        }
        __syncthreads();

        gemm_mma<true>(xh, xl, wh, wl, bv + li * D, sa, warp, lane);   // v -> sa (q dead)
        __syncthreads();

        // ---- tiled attn: warp (wb, wsub); stream each V row once ----
        {
            float4 acc[4];
#pragma unroll
            for (int t = 0; t < 4; ++t) acc[t] = make_float4(0.f, 0.f, 0.f, 0.f);
            for (int ki = 0; ki < S; ++ki) {
                const float4 vv = *(const float4*)&sa[(wb * S + ki) * D + c4];
#pragma unroll
                for (int t = 0; t < 4; ++t) {
                    const int row = wsub + 5 * t;
                    if (row < S) {
                        const float pv = ss[wb * S * S + row * S + ki];
                        FMA4(acc[t], pv, vv)
                    }
                }
            }
#pragma unroll
            for (int t = 0; t < 4; ++t) {
                const int row = wsub + 5 * t;
                if (row < S) {
                    const float m = smask[wb * S + row];
                    acc[t].x *= m; acc[t].y *= m; acc[t].z *= m; acc[t].w *= m;
                    *(float4*)&sb[(wb * S + row) * D + c4] = acc[t];
                }
            }
        }
        __syncthreads();

        // x = LN(x + attn) + fused split
        ln_add_split(sx, sb, g1 + li * D, b1 + li * D, xh, xl, warp, lane);
        stage_w(Wd + li * D * D, wh, wl, tid);
        __syncthreads();

        gemm_mma<false>(xh, xl, wh, wl, bd + li * D, sa, warp, lane);  // d -> sa
        __syncthreads();

        // x = LN(x + d) + fused split (feeds next layer's QKV)
        ln_add_split(sx, sa, g2 + li * D, b2 + li * D, xh, xl, warp, lane);
        __syncthreads();
    }

    // ---- output projection: out = x@Wo + bo (fp32 SIMT) ----
    for (int i = tid; i < D * 32; i += NTHREADS) {
        const int k = i >> 5, n = i & 31;
        swb[i] = (n < V) ? Wo[k * V + n] : 0.f;
    }
    __syncthreads();
    for (int r = warp; r < ROWS; r += NWARPS) {
        if (lane < V) {
            float acc = bo[lane];
            const float* xr = &sx[r * D];
#pragma unroll 8
            for (int k = 0; k < D; ++k) acc += xr[k] * swb[k * 32 + lane];
            out[(base_row + r) * V + lane] = acc;
        }
    }
}

// ---------------------------------------------------------------------------
extern "C" void kernel_launch(void* const* d_in, const int* in_sizes, int n_in,
                              void* d_out, int out_size) {
    (void)in_sizes; (void)n_in; (void)out_size;
    const float* X    = (const float*)d_in[0];
    const float* mask = (const float*)d_in[1];
    const float* seg  = (const float*)d_in[2];
    const float* We   = (const float*)d_in[3];
    const float* be   = (const float*)d_in[4];
    const float* Wp   = (const float*)d_in[5];
    const float* bp   = (const float*)d_in[6];
    const float* Wsg  = (const float*)d_in[7];
    const float* bsg  = (const float*)d_in[8];
    const float* g1   = (const float*)d_in[9];
    const float* b1   = (const float*)d_in[10];
    const float* Wq   = (const float*)d_in[11];
    const float* bq   = (const float*)d_in[12];
    const float* Wk   = (const float*)d_in[13];
    const float* bk   = (const float*)d_in[14];
    const float* Wv   = (const float*)d_in[15];
    const float* bv   = (const float*)d_in[16];
    const float* g2   = (const float*)d_in[17];
    const float* b2   = (const float*)d_in[18];
    const float* Wd   = (const float*)d_in[19];
    const float* bd   = (const float*)d_in[20];
    const float* Wo   = (const float*)d_in[21];
    const float* bo   = (const float*)d_in[22];
    float* out = (float*)d_out;

    cudaFuncSetAttribute(artistbert_kernel,
                         cudaFuncAttributeMaxDynamicSharedMemorySize, SMEM_BYTES);
    artistbert_kernel<<<BB / BQ, NTHREADS, SMEM_BYTES>>>(
        X, mask, seg, We, be, Wp, bp, Wsg, bsg, g1, b1,
        Wq, bq, Wk, bk, Wv, bv, g2, b2, Wd, bd, Wo, bo, out);
}

// round 10
// speedup vs baseline: 1.6809x; 1.0123x over previous
#include <cuda_runtime.h>
#include <cstdint>

// Problem constants
#define BB   16384
#define S    17
#define V    29
#define D    128
#define NSEG 4
#define NL   6
#define EPS  1e-5f

// Tiling
#define BQ       4
#define ROWS     (BQ * S)       // 68
#define NTHREADS 640            // 20 warps = 5 Mtiles x 4 Ngroups (GEMM), 4 batches x 5 subs (attn)
#define NWARPS   20
#define XW       68             // xh/xl row stride in words (68%32==4 -> conflict-free)
#define WW       68             // wh/wl col stride in words
#define AS       132            // sa/sb row stride (132%32==4 -> conflict-free GEMM stores)

// Shared memory layout (float/word offsets)
#define OFF_SX  0                        // x residual  [68][128] fp32
#define OFF_SA  8704                     // scratch A   [68][AS] fp32
#define OFF_SB  17680                    // scratch B   [68][AS] fp32
#define OFF_XH  26656                    // x hi  [80][XW] bf16x2 words (rows 68-79 zero pad)
#define OFF_XL  32096                    // x lo
#define OFF_WH  37536                    // W hi  [128][WW] bf16x2 words (transposed, k-pairs)
#define OFF_WL  46240                    // W lo
#define OFF_SC  54944                    // scores [4][17][17]
#define OFF_M   56100                    // mask [68]
#define OFF_SEG 56168                    // seg one-hot [68][4]
#define SMEM_FLOATS 56440
#define SMEM_BYTES  (SMEM_FLOATS * 4)    // 225,760 B

#define FMA4(_acc_, _s_, _w_)                                                  \
    _acc_.x += (_s_) * (_w_).x; _acc_.y += (_s_) * (_w_).y;                    \
    _acc_.z += (_s_) * (_w_).z; _acc_.w += (_s_) * (_w_).w;

// ---------------------------------------------------------------------------
// bf16 helpers
// ---------------------------------------------------------------------------
// pack(lo_k, hi_k): low 16 bits = lower-k element (mma convention)
__device__ __forceinline__ uint32_t bf16x2_pack(float lo_k, float hi_k) {
    uint32_t r;
    asm("cvt.rn.bf16x2.f32 %0, %1, %2;" : "=r"(r) : "f"(hi_k), "f"(lo_k));
    return r;
}

__device__ __forceinline__ void mma_bf16(float* d, const uint32_t* a, const uint32_t* b) {
    asm volatile(
        "mma.sync.aligned.m16n8k16.row.col.f32.bf16.bf16.f32 "
        "{%0,%1,%2,%3}, {%4,%5,%6,%7}, {%8,%9}, {%0,%1,%2,%3};"
        : "+f"(d[0]), "+f"(d[1]), "+f"(d[2]), "+f"(d[3])
        : "r"(a[0]), "r"(a[1]), "r"(a[2]), "r"(a[3]), "r"(b[0]), "r"(b[1]));
}

// Split a float4 (cols c..c+3) into two bf16x2 hi words + two lo words and
// store at word index r*XW + (c>>1).
__device__ __forceinline__ void store_split4(uint32_t* __restrict__ xh,
                                             uint32_t* __restrict__ xl,
                                             int r, int c, float4 o4) {
    const uint32_t h0 = bf16x2_pack(o4.x, o4.y);
    const uint32_t h1 = bf16x2_pack(o4.z, o4.w);
    const float a0 = __uint_as_float(h0 << 16);
    const float a1 = __uint_as_float(h0 & 0xFFFF0000u);
    const float a2 = __uint_as_float(h1 << 16);
    const float a3 = __uint_as_float(h1 & 0xFFFF0000u);
    const uint32_t l0 = bf16x2_pack(o4.x - a0, o4.y - a1);
    const uint32_t l1 = bf16x2_pack(o4.z - a2, o4.w - a3);
    uint2 hh; hh.x = h0; hh.y = h1;
    uint2 ll; ll.x = l0; ll.y = l1;
    *(uint2*)&xh[r * XW + (c >> 1)] = hh;
    *(uint2*)&xl[r * XW + (c >> 1)] = ll;
}

// Stage W (fp32 row-major [k][n]) -> wh/wl transposed k-pair-packed bf16x2.
__device__ __forceinline__ void stage_w(const float* __restrict__ gW,
                                        uint32_t* __restrict__ wh,
                                        uint32_t* __restrict__ wl, int tid) {
    for (int i = tid; i < 64 * D; i += NTHREADS) {
        const int j = i >> 7, n = i & 127;       // kpair j, output col n
        const float w0 = __ldg(&gW[(2 * j) * D + n]);
        const float w1 = __ldg(&gW[(2 * j + 1) * D + n]);
        const uint32_t h = bf16x2_pack(w0, w1);
        const float h0 = __uint_as_float(h << 16);
        const float h1 = __uint_as_float(h & 0xFFFF0000u);
        const uint32_t l = bf16x2_pack(w0 - h0, w1 - h1);
        wh[n * WW + j] = h;
        wl[n * WW + j] = l;
    }
}

// dst[r][n] = (relu?) x[r][:] . W[:][n] + bias[n]  via bf16 3-pass mma.
// dst has row stride AS (conflict-free stores).
template <bool RELU>
__device__ __forceinline__ void gemm_mma(const uint32_t* __restrict__ xh,
                                         const uint32_t* __restrict__ xl,
                                         const uint32_t* __restrict__ wh,
                                         const uint32_t* __restrict__ wl,
                                         const float* __restrict__ bias,
                                         float* __restrict__ dst,
                                         int warp, int lane) {
    const int mt = warp >> 2, ng = warp & 3;
    const int g = lane >> 2, t = lane & 3;
    const int r0 = mt * 16, n0 = ng * 32;
    const uint32_t* xa = xh + (r0 + g) * XW + t;
    const uint32_t* xb = xh + (r0 + g + 8) * XW + t;
    const uint32_t* ya = xl + (r0 + g) * XW + t;
    const uint32_t* yb = xl + (r0 + g + 8) * XW + t;

    float d[4][4] = {};
#pragma unroll
    for (int ks = 0; ks < 8; ++ks) {
        const int kb = ks * 8;
        uint32_t ah[4], al[4];
        ah[0] = xa[kb]; ah[1] = xb[kb]; ah[2] = xa[kb + 4]; ah[3] = xb[kb + 4];
        al[0] = ya[kb]; al[1] = yb[kb]; al[2] = ya[kb + 4]; al[3] = yb[kb + 4];
#pragma unroll
        for (int ns = 0; ns < 4; ++ns) {
            const int cw = (n0 + ns * 8 + g) * WW + kb;
            uint32_t bh[2], bl[2];
            bh[0] = wh[cw + t]; bh[1] = wh[cw + t + 4];
            bl[0] = wl[cw + t]; bl[1] = wl[cw + t + 4];
            mma_bf16(d[ns], ah, bh);
            mma_bf16(d[ns], ah, bl);
            mma_bf16(d[ns], al, bh);
        }
    }
    const int ra = r0 + g, rb = r0 + g + 8;
    const bool va = ra < ROWS, vb = rb < ROWS;
#pragma unroll
    for (int ns = 0; ns < 4; ++ns) {
        const int c = n0 + ns * 8 + 2 * t;
        const float b0 = __ldg(&bias[c]), b1 = __ldg(&bias[c + 1]);
        float v0 = d[ns][0] + b0, v1 = d[ns][1] + b1;
        float v2 = d[ns][2] + b0, v3 = d[ns][3] + b1;
        if (RELU) {
            v0 = fmaxf(v0, 0.f); v1 = fmaxf(v1, 0.f);
            v2 = fmaxf(v2, 0.f); v3 = fmaxf(v3, 0.f);
        }
        float2 p0; p0.x = v0; p0.y = v1;
        float2 p1; p1.x = v2; p1.y = v3;
        if (va) *(float2*)&dst[ra * AS + c] = p0;
        if (vb) *(float2*)&dst[rb * AS + c] = p1;
    }
}

// x[r] = LN(x[r] + add[r]) * g + b, ALSO writes the bf16 hi/lo split of the
// new x. add has row stride AS; sx has row stride D.
__device__ __forceinline__ void ln_add_split(float* __restrict__ sx,
                                             const float* __restrict__ add,
                                             const float* __restrict__ g,
                                             const float* __restrict__ b,
                                             uint32_t* __restrict__ xh,
                                             uint32_t* __restrict__ xl,
                                             int warp, int lane) {
    const int c = lane * 4;
    const float4 gv = *(const float4*)&g[c];
    const float4 bvec = *(const float4*)&b[c];
    for (int r = warp; r < ROWS; r += NWARPS) {
        const float4 xv = *(const float4*)&sx[r * D + c];
        const float4 av = *(const float4*)&add[r * AS + c];
        float4 t;
        t.x = xv.x + av.x; t.y = xv.y + av.y; t.z = xv.z + av.z; t.w = xv.w + av.w;
        float s  = t.x + t.y + t.z + t.w;
        float sq = t.x * t.x + t.y * t.y + t.z * t.z + t.w * t.w;
#pragma unroll
        for (int o = 16; o; o >>= 1) {
            s  += __shfl_xor_sync(0xFFFFFFFFu, s,  o);
            sq += __shfl_xor_sync(0xFFFFFFFFu, sq, o);
        }
        const float mu  = s * (1.0f / D);
        const float var = sq * (1.0f / D) - mu * mu;
        const float inv = rsqrtf(var + EPS);
        float4 o4;
        o4.x = (t.x - mu) * inv * gv.x + bvec.x;
        o4.y = (t.y - mu) * inv * gv.y + bvec.y;
        o4.z = (t.z - mu) * inv * gv.z + bvec.z;
        o4.w = (t.w - mu) * inv * gv.w + bvec.w;
        *(float4*)&sx[r * D + c] = o4;
        store_split4(xh, xl, r, c, o4);
    }
}

// ---------------------------------------------------------------------------
__global__ __launch_bounds__(NTHREADS, 1)
void artistbert_kernel(const float* __restrict__ X,    const float* __restrict__ mask_in,
                       const float* __restrict__ seg_in,
                       const float* __restrict__ We,   const float* __restrict__ be,
                       const float* __restrict__ Wp,   const float* __restrict__ bp,
                       const float* __restrict__ Wsg,  const float* __restrict__ bsg,
                       const float* __restrict__ g1,   const float* __restrict__ b1,
                       const float* __restrict__ Wq,   const float* __restrict__ bq,
                       const float* __restrict__ Wk,   const float* __restrict__ bk,
                       const float* __restrict__ Wv,   const float* __restrict__ bv,
                       const float* __restrict__ g2,   const float* __restrict__ b2,
                       const float* __restrict__ Wd,   const float* __restrict__ bd,
                       const float* __restrict__ Wo,   const float* __restrict__ bo,
                       float* __restrict__ out) {
    extern __shared__ float sm[];
    float*    sx    = sm + OFF_SX;
    float*    sa    = sm + OFF_SA;
    float*    sb    = sm + OFF_SB;
    uint32_t* xh    = (uint32_t*)(sm + OFF_XH);
    uint32_t* xl    = (uint32_t*)(sm + OFF_XL);
    uint32_t* wh    = (uint32_t*)(sm + OFF_WH);
    uint32_t* wl    = (uint32_t*)(sm + OFF_WL);
    float*    ss    = sm + OFF_SC;
    float*    smask = sm + OFF_M;
    float*    sseg  = sm + OFF_SEG;

    const int tid  = threadIdx.x;
    const int warp = tid >> 5;
    const int lane = tid & 31;
    const int c4   = lane * 4;
    const int wb   = warp / 5;          // batch for scores/attn tiling (0..3)
    const int wsub = warp - wb * 5;     // sub-warp (0..4)
    const int  b0       = blockIdx.x * BQ;
    const long base_row = (long)b0 * S;

    // zero xh/xl (incl. pad rows 68-79; live rows get overwritten)
    for (int i = tid; i < 80 * XW; i += NTHREADS) { xh[i] = 0u; xl[i] = 0u; }

    // ---- stage embedding tables + per-tile inputs ----
    float* swb = sm + OFF_WH;                      // reuse W region for We
    for (int i = tid; i < V * D; i += NTHREADS) swb[i] = We[i];
    for (int i = tid; i < S * D; i += NTHREADS) {
        const int d = i & (D - 1);
        sa[i] = Wp[i] + bp[d] + be[d] + bsg[d];    // combined positional + biases (flat use)
    }
    for (int i = tid; i < NSEG * D; i += NTHREADS) sa[S * D + i] = Wsg[i];
    {
        const float* Xb = X + base_row * V;
        for (int i = tid; i < ROWS * V; i += NTHREADS) sb[i] = Xb[i];
    }
    for (int i = tid; i < ROWS; i += NTHREADS) smask[i] = mask_in[base_row + i];
    {
        const float* Sg = seg_in + base_row * NSEG;
        for (int i = tid; i < ROWS * NSEG; i += NTHREADS) sseg[i] = Sg[i];
    }
    __syncthreads();

    // ---- embedding: sx = X@We + posc + seg@Wsg (fp32 SIMT) + fused split ----
    for (int r = warp; r < ROWS; r += NWARPS) {
        const int s = r % S;
        float4 acc = *(const float4*)&sa[s * D + c4];
#pragma unroll
        for (int j = 0; j < NSEG; ++j) {
            const float svv = sseg[r * NSEG + j];
            const float4 wv = *(const float4*)&sa[S * D + j * D + c4];
            FMA4(acc, svv, wv)
        }
        const float* xr = &sb[r * V];
#pragma unroll
        for (int vtok = 0; vtok < V; ++vtok) {
            const float xv = xr[vtok];
            const float4 wv = *(const float4*)&swb[vtok * D + c4];
            FMA4(acc, xv, wv)
        }
        *(float4*)&sx[r * D + c4] = acc;
        store_split4(xh, xl, r, c4, acc);
    }
    __syncthreads();

    // ---- transformer layers ----
    for (int li = 0; li < NL; ++li) {
        // stage Wq (x splits already available from prev epilogue)
        stage_w(Wq + li * D * D, wh, wl, tid);
        __syncthreads();

        gemm_mma<true>(xh, xl, wh, wl, bq + li * D, sa, warp, lane);   // q -> sa
        __syncthreads();

        stage_w(Wk + li * D * D, wh, wl, tid);
        __syncthreads();

        gemm_mma<true>(xh, xl, wh, wl, bk + li * D, sb, warp, lane);   // k -> sb
        __syncthreads();

        // ---- tiled scores: warp (wb, wsub) handles q-rows {wsub+5t} of batch wb.
        {
            float4 qf[4];
#pragma unroll
            for (int t = 0; t < 4; ++t) {
                const int row = wsub + 5 * t;
                qf[t] = (row < S) ? *(const float4*)&sa[(wb * S + row) * AS + c4]
                                  : make_float4(0.f, 0.f, 0.f, 0.f);
            }
            for (int ki = 0; ki < S; ++ki) {
                const float4 kv = *(const float4*)&sb[(wb * S + ki) * AS + c4];
#pragma unroll
                for (int t = 0; t < 4; ++t) {
                    const int row = wsub + 5 * t;
                    if (row < S) {
                        float p = qf[t].x * kv.x + qf[t].y * kv.y
                                + qf[t].z * kv.z + qf[t].w * kv.w;
#pragma unroll
                        for (int o = 16; o; o >>= 1) p += __shfl_xor_sync(0xFFFFFFFFu, p, o);
                        if (lane == 0) ss[wb * S * S + row * S + ki] = p;
                    }
                }
            }
        }
        stage_w(Wv + li * D * D, wh, wl, tid);
        __syncthreads();

        // softmax (thread per (b,qi) row)
        if (tid < ROWS) {
            float* row = &ss[(tid / S) * S * S + (tid % S) * S];
            float mx = row[0];
#pragma unroll
            for (int j = 1; j < S; ++j) mx = fmaxf(mx, row[j]);
            float sum = 0.f;
#pragma unroll
            for (int j = 0; j < S; ++j) { const float e = __expf(row[j] - mx); row[j] = e; sum += e; }
            const float inv = 1.0f / sum;
#pragma unroll
            for (int j = 0; j < S; ++j) row[j] *= inv;
        }
        __syncthreads();

        gemm_mma<true>(xh, xl, wh, wl, bv + li * D, sa, warp, lane);   // v -> sa (q dead)
        __syncthreads();

        // ---- tiled attn: warp (wb, wsub); stream each V row once ----
        {
            float4 acc[4];
#pragma unroll
            for (int t = 0; t < 4; ++t) acc[t] = make_float4(0.f, 0.f, 0.f, 0.f);
            for (int ki = 0; ki < S; ++ki) {
                const float4 vv = *(const float4*)&sa[(wb * S + ki) * AS + c4];
#pragma unroll
                for (int t = 0; t < 4; ++t) {
                    const int row = wsub + 5 * t;
                    if (row < S) {
                        const float pv = ss[wb * S * S + row * S + ki];
                        FMA4(acc[t], pv, vv)
                    }
                }
            }
#pragma unroll
            for (int t = 0; t < 4; ++t) {
                const int row = wsub + 5 * t;
                if (row < S) {
                    const float m = smask[wb * S + row];
                    acc[t].x *= m; acc[t].y *= m; acc[t].z *= m; acc[t].w *= m;
                    *(float4*)&sb[(wb * S + row) * AS + c4] = acc[t];
                }
            }
        }
        __syncthreads();

        // x = LN(x + attn) + fused split
        ln_add_split(sx, sb, g1 + li * D, b1 + li * D, xh, xl, warp, lane);
        stage_w(Wd + li * D * D, wh, wl, tid);
        __syncthreads();

        gemm_mma<false>(xh, xl, wh, wl, bd + li * D, sa, warp, lane);  // d -> sa
        __syncthreads();

        // x = LN(x + d) + fused split (feeds next layer's QKV)
        ln_add_split(sx, sa, g2 + li * D, b2 + li * D, xh, xl, warp, lane);
        __syncthreads();
    }

    // ---- output projection: out = x@Wo + bo (fp32 SIMT) ----
    for (int i = tid; i < D * 32; i += NTHREADS) {
        const int k = i >> 5, n = i & 31;
        swb[i] = (n < V) ? Wo[k * V + n] : 0.f;
    }
    __syncthreads();
    for (int r = warp; r < ROWS; r += NWARPS) {
        if (lane < V) {
            float acc = bo[lane];
            const float* xr = &sx[r * D];
#pragma unroll 8
            for (int k = 0; k < D; ++k) acc += xr[k] * swb[k * 32 + lane];
            out[(base_row + r) * V + lane] = acc;
        }
    }
}

// ---------------------------------------------------------------------------
extern "C" void kernel_launch(void* const* d_in, const int* in_sizes, int n_in,
                              void* d_out, int out_size) {
    (void)in_sizes; (void)n_in; (void)out_size;
    const float* X    = (const float*)d_in[0];
    const float* mask = (const float*)d_in[1];
    const float* seg  = (const float*)d_in[2];
    const float* We   = (const float*)d_in[3];
    const float* be   = (const float*)d_in[4];
    const float* Wp   = (const float*)d_in[5];
    const float* bp   = (const float*)d_in[6];
    const float* Wsg  = (const float*)d_in[7];
    const float* bsg  = (const float*)d_in[8];
    const float* g1   = (const float*)d_in[9];
    const float* b1   = (const float*)d_in[10];
    const float* Wq   = (const float*)d_in[11];
    const float* bq   = (const float*)d_in[12];
    const float* Wk   = (const float*)d_in[13];
    const float* bk   = (const float*)d_in[14];
    const float* Wv   = (const float*)d_in[15];
    const float* bv   = (const float*)d_in[16];
    const float* g2   = (const float*)d_in[17];
    const float* b2   = (const float*)d_in[18];
    const float* Wd   = (const float*)d_in[19];
    const float* bd   = (const float*)d_in[20];
    const float* Wo   = (const float*)d_in[21];
    const float* bo   = (const float*)d_in[22];
    float* out = (float*)d_out;

    cudaFuncSetAttribute(artistbert_kernel,
                         cudaFuncAttributeMaxDynamicSharedMemorySize, SMEM_BYTES);
    artistbert_kernel<<<BB / BQ, NTHREADS, SMEM_BYTES>>>(
        X, mask, seg, We, be, Wp, bp, Wsg, bsg, g1, b1,
        Wq, bq, Wk, bk, Wv, bv, g2, b2, Wd, bd, Wo, bo, out);
}

// round 11
// speedup vs baseline: 1.8375x; 1.0932x over previous
#include <cuda_runtime.h>
#include <cstdint>

// Problem constants
#define BB   16384
#define S    17
#define V    29
#define D    128
#define NSEG 4
#define NL   6
#define EPS  1e-5f

// Tiling
#define BQ       4
#define ROWS     (BQ * S)       // 68
#define NTHREADS 640            // 20 warps = 5 Mtiles x 4 Ngroups (GEMM), 4 batches x 5 subs (attn)
#define NWARPS   20
#define XW       68             // xh/xl row stride in words (68%32==4 -> conflict-free)
#define WW       68             // wh/wl col stride in words
#define AS       132            // sa/sb row stride (132%32==4 -> conflict-free GEMM stores)
#define WIMG_W   17408          // words per baked matrix image (hi 8704 + lo 8704)

// Shared memory layout (float/word offsets)
#define OFF_SX  0                        // x residual  [68][128] fp32
#define OFF_SA  8704                     // scratch A   [68][AS] fp32
#define OFF_SB  17680                    // scratch B   [68][AS] fp32
#define OFF_XH  26656                    // x hi  [80][XW] bf16x2 words
#define OFF_XL  32096                    // x lo
#define OFF_WH  37536                    // W hi  [128][WW] bf16x2 words (transposed, k-pairs)
#define OFF_WL  46240                    // W lo (contiguous after WH)
#define OFF_SC  54944                    // scores [4][17][17]
#define OFF_M   56100                    // mask [68]
#define OFF_SEG 56168                    // seg one-hot [68][4]
#define SMEM_FLOATS 56440
#define SMEM_BYTES  (SMEM_FLOATS * 4)    // 225,760 B

// Baked weight images: [NL][4 matrices][hi|lo padded layout]
__device__ uint32_t g_wimg[NL * 4 * WIMG_W];

#define FMA4(_acc_, _s_, _w_)                                                  \
    _acc_.x += (_s_) * (_w_).x; _acc_.y += (_s_) * (_w_).y;                    \
    _acc_.z += (_s_) * (_w_).z; _acc_.w += (_s_) * (_w_).w;

// ---------------------------------------------------------------------------
// bf16 helpers
// ---------------------------------------------------------------------------
__device__ __forceinline__ uint32_t bf16x2_pack(float lo_k, float hi_k) {
    uint32_t r;
    asm("cvt.rn.bf16x2.f32 %0, %1, %2;" : "=r"(r) : "f"(hi_k), "f"(lo_k));
    return r;
}

__device__ __forceinline__ void mma_bf16(float* d, const uint32_t* a, const uint32_t* b) {
    asm volatile(
        "mma.sync.aligned.m16n8k16.row.col.f32.bf16.bf16.f32 "
        "{%0,%1,%2,%3}, {%4,%5,%6,%7}, {%8,%9}, {%0,%1,%2,%3};"
        : "+f"(d[0]), "+f"(d[1]), "+f"(d[2]), "+f"(d[3])
        : "r"(a[0]), "r"(a[1]), "r"(a[2]), "r"(a[3]), "r"(b[0]), "r"(b[1]));
}

__device__ __forceinline__ void store_split4(uint32_t* __restrict__ xh,
                                             uint32_t* __restrict__ xl,
                                             int r, int c, float4 o4) {
    const uint32_t h0 = bf16x2_pack(o4.x, o4.y);
    const uint32_t h1 = bf16x2_pack(o4.z, o4.w);
    const float a0 = __uint_as_float(h0 << 16);
    const float a1 = __uint_as_float(h0 & 0xFFFF0000u);
    const float a2 = __uint_as_float(h1 << 16);
    const float a3 = __uint_as_float(h1 & 0xFFFF0000u);
    const uint32_t l0 = bf16x2_pack(o4.x - a0, o4.y - a1);
    const uint32_t l1 = bf16x2_pack(o4.z - a2, o4.w - a3);
    uint2 hh; hh.x = h0; hh.y = h1;
    uint2 ll; ll.x = l0; ll.y = l1;
    *(uint2*)&xh[r * XW + (c >> 1)] = hh;
    *(uint2*)&xl[r * XW + (c >> 1)] = ll;
}

// ---------------------------------------------------------------------------
// Pre-kernel: bake W (fp32 row-major [k][n]) into transposed k-pair-packed
// bf16x2 hi/lo images with the exact smem layout (col stride WW).
// ---------------------------------------------------------------------------
__global__ void bake_kernel(const float* __restrict__ Wq, const float* __restrict__ Wk,
                            const float* __restrict__ Wv, const float* __restrict__ Wd) {
    const int idx = blockIdx.x * blockDim.x + threadIdx.x;
    if (idx >= NL * 4 * 64 * D) return;
    const int li = idx >> 15;              // 4*8192 per layer
    const int m  = (idx >> 13) & 3;
    const int e  = idx & 8191;
    const int j  = e >> 7;                 // kpair 0..63
    const int n  = e & 127;                // output col
    const float* src = (m == 0) ? Wq : (m == 1) ? Wk : (m == 2) ? Wv : Wd;
    const float w0 = src[li * D * D + (2 * j) * D + n];
    const float w1 = src[li * D * D + (2 * j + 1) * D + n];
    const uint32_t h = bf16x2_pack(w0, w1);
    const float h0 = __uint_as_float(h << 16);
    const float h1 = __uint_as_float(h & 0xFFFF0000u);
    const uint32_t l = bf16x2_pack(w0 - h0, w1 - h1);
    uint32_t* img = g_wimg + (li * 4 + m) * WIMG_W;
    img[n * WW + j]        = h;
    img[8704 + n * WW + j] = l;
}

// Copy one baked matrix image (17408 words) into smem wh|wl region.
__device__ __forceinline__ void stage_copy(int mat_idx, uint32_t* __restrict__ whl,
                                           int tid) {
    const float4* src = (const float4*)&g_wimg[mat_idx * WIMG_W];
    float4* dst = (float4*)whl;
#pragma unroll
    for (int i = 0; i < 7; ++i) {
        const int idx = tid + i * NTHREADS;
        if (idx < WIMG_W / 4) dst[idx] = __ldg(&src[idx]);
    }
}

// dst[r][n] = (relu?) x[r][:] . W[:][n] + bias[n]  via bf16 3-pass mma.
template <bool RELU>
__device__ __forceinline__ void gemm_mma(const uint32_t* __restrict__ xh,
                                         const uint32_t* __restrict__ xl,
                                         const uint32_t* __restrict__ wh,
                                         const uint32_t* __restrict__ wl,
                                         const float* __restrict__ bias,
                                         float* __restrict__ dst,
                                         int warp, int lane) {
    const int mt = warp >> 2, ng = warp & 3;
    const int g = lane >> 2, t = lane & 3;
    const int r0 = mt * 16, n0 = ng * 32;
    const uint32_t* xa = xh + (r0 + g) * XW + t;
    const uint32_t* xb = xh + (r0 + g + 8) * XW + t;
    const uint32_t* ya = xl + (r0 + g) * XW + t;
    const uint32_t* yb = xl + (r0 + g + 8) * XW + t;

    float d[4][4] = {};
#pragma unroll
    for (int ks = 0; ks < 8; ++ks) {
        const int kb = ks * 8;
        uint32_t ah[4], al[4];
        ah[0] = xa[kb]; ah[1] = xb[kb]; ah[2] = xa[kb + 4]; ah[3] = xb[kb + 4];
        al[0] = ya[kb]; al[1] = yb[kb]; al[2] = ya[kb + 4]; al[3] = yb[kb + 4];
#pragma unroll
        for (int ns = 0; ns < 4; ++ns) {
            const int cw = (n0 + ns * 8 + g) * WW + kb;
            uint32_t bh[2], bl[2];
            bh[0] = wh[cw + t]; bh[1] = wh[cw + t + 4];
            bl[0] = wl[cw + t]; bl[1] = wl[cw + t + 4];
            mma_bf16(d[ns], ah, bh);
            mma_bf16(d[ns], ah, bl);
            mma_bf16(d[ns], al, bh);
        }
    }
    const int ra = r0 + g, rb = r0 + g + 8;
    const bool va = ra < ROWS, vb = rb < ROWS;
#pragma unroll
    for (int ns = 0; ns < 4; ++ns) {
        const int c = n0 + ns * 8 + 2 * t;
        const float b0 = __ldg(&bias[c]), b1 = __ldg(&bias[c + 1]);
        float v0 = d[ns][0] + b0, v1 = d[ns][1] + b1;
        float v2 = d[ns][2] + b0, v3 = d[ns][3] + b1;
        if (RELU) {
            v0 = fmaxf(v0, 0.f); v1 = fmaxf(v1, 0.f);
            v2 = fmaxf(v2, 0.f); v3 = fmaxf(v3, 0.f);
        }
        float2 p0; p0.x = v0; p0.y = v1;
        float2 p1; p1.x = v2; p1.y = v3;
        if (va) *(float2*)&dst[ra * AS + c] = p0;
        if (vb) *(float2*)&dst[rb * AS + c] = p1;
    }
}

// x[r] = LN(x[r] + add[r]) * g + b, with fused bf16 split. add stride AS.
__device__ __forceinline__ void ln_add_split(float* __restrict__ sx,
                                             const float* __restrict__ add,
                                             const float* __restrict__ g,
                                             const float* __restrict__ b,
                                             uint32_t* __restrict__ xh,
                                             uint32_t* __restrict__ xl,
                                             int warp, int lane) {
    const int c = lane * 4;
    const float4 gv = *(const float4*)&g[c];
    const float4 bvec = *(const float4*)&b[c];
    for (int r = warp; r < ROWS; r += NWARPS) {
        const float4 xv = *(const float4*)&sx[r * D + c];
        const float4 av = *(const float4*)&add[r * AS + c];
        float4 t;
        t.x = xv.x + av.x; t.y = xv.y + av.y; t.z = xv.z + av.z; t.w = xv.w + av.w;
        float s  = t.x + t.y + t.z + t.w;
        float sq = t.x * t.x + t.y * t.y + t.z * t.z + t.w * t.w;
#pragma unroll
        for (int o = 16; o; o >>= 1) {
            s  += __shfl_xor_sync(0xFFFFFFFFu, s,  o);
            sq += __shfl_xor_sync(0xFFFFFFFFu, sq, o);
        }
        const float mu  = s * (1.0f / D);
        const float var = sq * (1.0f / D) - mu * mu;
        const float inv = rsqrtf(var + EPS);
        float4 o4;
        o4.x = (t.x - mu) * inv * gv.x + bvec.x;
        o4.y = (t.y - mu) * inv * gv.y + bvec.y;
        o4.z = (t.z - mu) * inv * gv.z + bvec.z;
        o4.w = (t.w - mu) * inv * gv.w + bvec.w;
        *(float4*)&sx[r * D + c] = o4;
        store_split4(xh, xl, r, c, o4);
    }
}

// ---------------------------------------------------------------------------
__global__ __launch_bounds__(NTHREADS, 1)
void artistbert_kernel(const float* __restrict__ X,    const float* __restrict__ mask_in,
                       const float* __restrict__ seg_in,
                       const float* __restrict__ We,   const float* __restrict__ be,
                       const float* __restrict__ Wp,   const float* __restrict__ bp,
                       const float* __restrict__ Wsg,  const float* __restrict__ bsg,
                       const float* __restrict__ g1,   const float* __restrict__ b1,
                       const float* __restrict__ bq,   const float* __restrict__ bk,
                       const float* __restrict__ bv,
                       const float* __restrict__ g2,   const float* __restrict__ b2,
                       const float* __restrict__ bd,
                       const float* __restrict__ Wo,   const float* __restrict__ bo,
                       float* __restrict__ out) {
    extern __shared__ float sm[];
    float*    sx    = sm + OFF_SX;
    float*    sa    = sm + OFF_SA;
    float*    sb    = sm + OFF_SB;
    uint32_t* xh    = (uint32_t*)(sm + OFF_XH);
    uint32_t* xl    = (uint32_t*)(sm + OFF_XL);
    uint32_t* wh    = (uint32_t*)(sm + OFF_WH);
    uint32_t* wl    = (uint32_t*)(sm + OFF_WL);
    uint32_t* whl   = wh;                        // contiguous hi|lo region
    float*    ss    = sm + OFF_SC;
    float*    smask = sm + OFF_M;
    float*    sseg  = sm + OFF_SEG;

    const int tid  = threadIdx.x;
    const int warp = tid >> 5;
    const int lane = tid & 31;
    const int c4   = lane * 4;
    const int wb   = warp / 5;          // batch for scores/attn tiling (0..3)
    const int wsub = warp - wb * 5;     // sub-warp (0..4)
    const int  b0       = blockIdx.x * BQ;
    const long base_row = (long)b0 * S;

    // zero xh/xl (incl. pad rows 68-79)
    for (int i = tid; i < 80 * XW; i += NTHREADS) { xh[i] = 0u; xl[i] = 0u; }

    // ---- stage embedding tables + per-tile inputs (We lives in sa now) ----
    float* swe = sa + S * D + NSEG * D;            // We [29][128] at sa+2688
    for (int i = tid; i < S * D; i += NTHREADS) {
        const int d = i & (D - 1);
        sa[i] = Wp[i] + bp[d] + be[d] + bsg[d];    // combined positional + biases
    }
    for (int i = tid; i < NSEG * D; i += NTHREADS) sa[S * D + i] = Wsg[i];
    for (int i = tid; i < V * D; i += NTHREADS) swe[i] = We[i];
    {
        const float* Xb = X + base_row * V;
        for (int i = tid; i < ROWS * V; i += NTHREADS) sb[i] = Xb[i];
    }
    for (int i = tid; i < ROWS; i += NTHREADS) smask[i] = mask_in[base_row + i];
    {
        const float* Sg = seg_in + base_row * NSEG;
        for (int i = tid; i < ROWS * NSEG; i += NTHREADS) sseg[i] = Sg[i];
    }
    __syncthreads();

    // ---- embedding + fused split  ||  stage Wq(layer 0) ----
    for (int r = warp; r < ROWS; r += NWARPS) {
        const int s = r % S;
        float4 acc = *(const float4*)&sa[s * D + c4];
#pragma unroll
        for (int j = 0; j < NSEG; ++j) {
            const float svv = sseg[r * NSEG + j];
            const float4 wv = *(const float4*)&sa[S * D + j * D + c4];
            FMA4(acc, svv, wv)
        }
        const float* xr = &sb[r * V];
#pragma unroll
        for (int vtok = 0; vtok < V; ++vtok) {
            const float xv = xr[vtok];
            const float4 wv = *(const float4*)&swe[vtok * D + c4];
            FMA4(acc, xv, wv)
        }
        *(float4*)&sx[r * D + c4] = acc;
        store_split4(xh, xl, r, c4, acc);
    }
    stage_copy(0, whl, tid);
    __syncthreads();

    // ---- transformer layers ----
    for (int li = 0; li < NL; ++li) {
        gemm_mma<true>(xh, xl, wh, wl, bq + li * D, sa, warp, lane);   // q -> sa
        __syncthreads();

        stage_copy(li * 4 + 1, whl, tid);                               // Wk
        __syncthreads();

        gemm_mma<true>(xh, xl, wh, wl, bk + li * D, sb, warp, lane);   // k -> sb
        __syncthreads();

        // ---- scores + softmax (warp (wb,wsub): rows {wsub+5t})  ||  stage Wv ----
        {
            float4 qf[4];
#pragma unroll
            for (int t = 0; t < 4; ++t) {
                const int row = wsub + 5 * t;
                qf[t] = (row < S) ? *(const float4*)&sa[(wb * S + row) * AS + c4]
                                  : make_float4(0.f, 0.f, 0.f, 0.f);
            }
            for (int ki = 0; ki < S; ++ki) {
                const float4 kv = *(const float4*)&sb[(wb * S + ki) * AS + c4];
#pragma unroll
                for (int t = 0; t < 4; ++t) {
                    const int row = wsub + 5 * t;
                    if (row < S) {
                        float p = qf[t].x * kv.x + qf[t].y * kv.y
                                + qf[t].z * kv.z + qf[t].w * kv.w;
#pragma unroll
                        for (int o = 16; o; o >>= 1) p += __shfl_xor_sync(0xFFFFFFFFu, p, o);
                        if (lane == 0) ss[wb * S * S + row * S + ki] = p;
                    }
                }
            }
            // warp-parallel softmax over each owned row
#pragma unroll
            for (int t = 0; t < 4; ++t) {
                const int row = wsub + 5 * t;
                if (row < S) {
                    float* rp = &ss[wb * S * S + row * S];
                    const float v = (lane < S) ? rp[lane] : -3.0e38f;
                    float mxv = v;
#pragma unroll
                    for (int o = 16; o; o >>= 1) mxv = fmaxf(mxv, __shfl_xor_sync(0xFFFFFFFFu, mxv, o));
                    const float e = (lane < S) ? __expf(v - mxv) : 0.f;
                    float sv = e;
#pragma unroll
                    for (int o = 16; o; o >>= 1) sv += __shfl_xor_sync(0xFFFFFFFFu, sv, o);
                    if (lane < S) rp[lane] = __fdividef(e, sv);
                }
            }
        }
        stage_copy(li * 4 + 2, whl, tid);                               // Wv
        __syncthreads();

        gemm_mma<true>(xh, xl, wh, wl, bv + li * D, sa, warp, lane);   // v -> sa
        __syncthreads();

        // ---- attn + mask + residual + LN1 + split (fused)  ||  stage Wd ----
        {
            float4 acc[4];
#pragma unroll
            for (int t = 0; t < 4; ++t) acc[t] = make_float4(0.f, 0.f, 0.f, 0.f);
            for (int ki = 0; ki < S; ++ki) {
                const float4 vv = *(const float4*)&sa[(wb * S + ki) * AS + c4];
#pragma unroll
                for (int t = 0; t < 4; ++t) {
                    const int row = wsub + 5 * t;
                    if (row < S) {
                        const float pv = ss[wb * S * S + row * S + ki];
                        FMA4(acc[t], pv, vv)
                    }
                }
            }
            const float4 gv = *(const float4*)&g1[li * D + c4];
            const float4 bvec = *(const float4*)&b1[li * D + c4];
#pragma unroll
            for (int t = 0; t < 4; ++t) {
                const int row = wsub + 5 * t;
                if (row < S) {
                    const int r = wb * S + row;
                    const float mk = smask[r];
                    const float4 xv = *(const float4*)&sx[r * D + c4];
                    float4 u;
                    u.x = xv.x + acc[t].x * mk; u.y = xv.y + acc[t].y * mk;
                    u.z = xv.z + acc[t].z * mk; u.w = xv.w + acc[t].w * mk;
                    float s  = u.x + u.y + u.z + u.w;
                    float sq = u.x * u.x + u.y * u.y + u.z * u.z + u.w * u.w;
#pragma unroll
                    for (int o = 16; o; o >>= 1) {
                        s  += __shfl_xor_sync(0xFFFFFFFFu, s,  o);
                        sq += __shfl_xor_sync(0xFFFFFFFFu, sq, o);
                    }
                    const float mu  = s * (1.0f / D);
                    const float var = sq * (1.0f / D) - mu * mu;
                    const float inv = rsqrtf(var + EPS);
                    float4 o4;
                    o4.x = (u.x - mu) * inv * gv.x + bvec.x;
                    o4.y = (u.y - mu) * inv * gv.y + bvec.y;
                    o4.z = (u.z - mu) * inv * gv.z + bvec.z;
                    o4.w = (u.w - mu) * inv * gv.w + bvec.w;
                    *(float4*)&sx[r * D + c4] = o4;
                    store_split4(xh, xl, r, c4, o4);
                }
            }
        }
        stage_copy(li * 4 + 3, whl, tid);                               // Wd
        __syncthreads();

        gemm_mma<false>(xh, xl, wh, wl, bd + li * D, sa, warp, lane);  // d -> sa
        __syncthreads();

        // x = LN(x + d) + split  ||  stage next layer's Wq
        ln_add_split(sx, sa, g2 + li * D, b2 + li * D, xh, xl, warp, lane);
        if (li + 1 < NL) stage_copy((li + 1) * 4, whl, tid);
        __syncthreads();
    }

    // ---- output projection: out = x@Wo + bo (fp32 SIMT) ----
    float* swb = sm + OFF_WH;
    for (int i = tid; i < D * 32; i += NTHREADS) {
        const int k = i >> 5, n = i & 31;
        swb[i] = (n < V) ? Wo[k * V + n] : 0.f;
    }
    __syncthreads();
    for (int r = warp; r < ROWS; r += NWARPS) {
        if (lane < V) {
            float acc = bo[lane];
            const float* xr = &sx[r * D];
#pragma unroll 8
            for (int k = 0; k < D; ++k) acc += xr[k] * swb[k * 32 + lane];
            out[(base_row + r) * V + lane] = acc;
        }
    }
}

// ---------------------------------------------------------------------------
extern "C" void kernel_launch(void* const* d_in, const int* in_sizes, int n_in,
                              void* d_out, int out_size) {
    (void)in_sizes; (void)n_in; (void)out_size;
    const float* X    = (const float*)d_in[0];
    const float* mask = (const float*)d_in[1];
    const float* seg  = (const float*)d_in[2];
    const float* We   = (const float*)d_in[3];
    const float* be   = (const float*)d_in[4];
    const float* Wp   = (const float*)d_in[5];
    const float* bp   = (const float*)d_in[6];
    const float* Wsg  = (const float*)d_in[7];
    const float* bsg  = (const float*)d_in[8];
    const float* g1   = (const float*)d_in[9];
    const float* b1   = (const float*)d_in[10];
    const float* Wq   = (const float*)d_in[11];
    const float* bq   = (const float*)d_in[12];
    const float* Wk   = (const float*)d_in[13];
    const float* bk   = (const float*)d_in[14];
    const float* Wv   = (const float*)d_in[15];
    const float* bv   = (const float*)d_in[16];
    const float* g2   = (const float*)d_in[17];
    const float* b2   = (const float*)d_in[18];
    const float* Wd   = (const float*)d_in[19];
    const float* bd   = (const float*)d_in[20];
    const float* Wo   = (const float*)d_in[21];
    const float* bo   = (const float*)d_in[22];
    float* out = (float*)d_out;

    // Bake bf16 hi/lo weight images (deterministic, graph-capturable)
    bake_kernel<<<(NL * 4 * 64 * D + 255) / 256, 256>>>(Wq, Wk, Wv, Wd);

    cudaFuncSetAttribute(artistbert_kernel,
                         cudaFuncAttributeMaxDynamicSharedMemorySize, SMEM_BYTES);
    artistbert_kernel<<<BB / BQ, NTHREADS, SMEM_BYTES>>>(
        X, mask, seg, We, be, Wp, bp, Wsg, bsg, g1, b1,
        bq, bk, bv, g2, b2, bd, Wo, bo, out);
}

// round 12
// speedup vs baseline: 1.9958x; 1.0861x over previous
#include <cuda_runtime.h>
#include <cstdint>

// Problem constants
#define BB   16384
#define S    17
#define V    29
#define D    128
#define NSEG 4
#define NL   6
#define EPS  1e-5f

// Tiling
#define BQ       4
#define ROWS     (BQ * S)       // 68
#define NTHREADS 640            // 20 warps
#define NWARPS   20
#define XW       68             // xh/xl row stride in words
#define WW       68             // wh col stride in words
#define AS       132            // sa/sb row stride
#define WHI_W    8704           // words per baked hi matrix image
#define WLO_W    8192           // words per baked lo matrix image (fragment-coalesced)

// Shared memory layout (float/word offsets)
#define OFF_SX  0                        // x residual  [68][128] fp32
#define OFF_SA  8704                     // scratch A   [68][AS] fp32
#define OFF_SB  17680                    // scratch B   [68][AS] fp32
#define OFF_XH  26656                    // x hi  [80][XW]
#define OFF_XL  32096                    // x lo
#define OFF_WHA 37536                    // W hi buffer A [128][WW]
#define OFF_WHB 46240                    // W hi buffer B
#define OFF_SC  54944                    // scores [4][17][17]
#define OFF_M   56100                    // mask [68]
#define OFF_SEG 56168                    // seg one-hot [68][4]
#define SMEM_FLOATS 56440
#define SMEM_BYTES  (SMEM_FLOATS * 4)    // 225,760 B

// Baked weights: hi (smem-staged layout), lo (L2-direct fragment layout)
__device__ uint32_t g_whi[NL * 4 * WHI_W];
__device__ uint32_t g_wlo[NL * 4 * WLO_W];

#define FMA4(_acc_, _s_, _w_)                                                  \
    _acc_.x += (_s_) * (_w_).x; _acc_.y += (_s_) * (_w_).y;                    \
    _acc_.z += (_s_) * (_w_).z; _acc_.w += (_s_) * (_w_).w;

// ---------------------------------------------------------------------------
__device__ __forceinline__ uint32_t bf16x2_pack(float lo_k, float hi_k) {
    uint32_t r;
    asm("cvt.rn.bf16x2.f32 %0, %1, %2;" : "=r"(r) : "f"(hi_k), "f"(lo_k));
    return r;
}

__device__ __forceinline__ void mma_bf16(float* d, const uint32_t* a, const uint32_t* b) {
    asm volatile(
        "mma.sync.aligned.m16n8k16.row.col.f32.bf16.bf16.f32 "
        "{%0,%1,%2,%3}, {%4,%5,%6,%7}, {%8,%9}, {%0,%1,%2,%3};"
        : "+f"(d[0]), "+f"(d[1]), "+f"(d[2]), "+f"(d[3])
        : "r"(a[0]), "r"(a[1]), "r"(a[2]), "r"(a[3]), "r"(b[0]), "r"(b[1]));
}

__device__ __forceinline__ void store_split4(uint32_t* __restrict__ xh,
                                             uint32_t* __restrict__ xl,
                                             int r, int c, float4 o4) {
    const uint32_t h0 = bf16x2_pack(o4.x, o4.y);
    const uint32_t h1 = bf16x2_pack(o4.z, o4.w);
    const float a0 = __uint_as_float(h0 << 16);
    const float a1 = __uint_as_float(h0 & 0xFFFF0000u);
    const float a2 = __uint_as_float(h1 << 16);
    const float a3 = __uint_as_float(h1 & 0xFFFF0000u);
    const uint32_t l0 = bf16x2_pack(o4.x - a0, o4.y - a1);
    const uint32_t l1 = bf16x2_pack(o4.z - a2, o4.w - a3);
    uint2 hh; hh.x = h0; hh.y = h1;
    uint2 ll; ll.x = l0; ll.y = l1;
    *(uint2*)&xh[r * XW + (c >> 1)] = hh;
    *(uint2*)&xl[r * XW + (c >> 1)] = ll;
}

// ---------------------------------------------------------------------------
// Pre-kernel: bake hi (transposed k-pair, col stride WW) and lo
// (fragment-coalesced: [ks][nb][g*8 + 2t + s]) images.
// ---------------------------------------------------------------------------
__global__ void bake_kernel(const float* __restrict__ Wq, const float* __restrict__ Wk,
                            const float* __restrict__ Wv, const float* __restrict__ Wd) {
    const int idx = blockIdx.x * blockDim.x + threadIdx.x;
    if (idx >= NL * 4 * 64 * D) return;
    const int li = idx >> 15;
    const int m  = (idx >> 13) & 3;
    const int e  = idx & 8191;
    const int j  = e >> 7;                 // kpair 0..63
    const int n  = e & 127;                // output col
    const float* src = (m == 0) ? Wq : (m == 1) ? Wk : (m == 2) ? Wv : Wd;
    const float w0 = src[li * D * D + (2 * j) * D + n];
    const float w1 = src[li * D * D + (2 * j + 1) * D + n];
    const uint32_t h = bf16x2_pack(w0, w1);
    const float h0 = __uint_as_float(h << 16);
    const float h1 = __uint_as_float(h & 0xFFFF0000u);
    const uint32_t l = bf16x2_pack(w0 - h0, w1 - h1);
    const int mat = li * 4 + m;
    g_whi[mat * WHI_W + n * WW + j] = h;
    // lo: ks = j/8, jr = j%8 -> (t = jr%4, s = jr/4); nb = n/8, g = n%8
    const int ks = j >> 3, jr = j & 7, t = jr & 3, s = jr >> 2;
    const int nb = n >> 3, g = n & 7;
    g_wlo[mat * WLO_W + ((ks * 16 + nb) << 6) + (g << 3) + 2 * t + s] = l;
}

// ---------------------------------------------------------------------------
// W-hi staging: register prefetch at phase top, smem commit at phase end.
// ---------------------------------------------------------------------------
__device__ __forceinline__ void stage_prefetch(int mat, float4* st, int tid) {
    const float4* src = (const float4*)&g_whi[mat * WHI_W];
#pragma unroll
    for (int i = 0; i < 4; ++i) {
        const int idx = tid + i * NTHREADS;
        if (idx < WHI_W / 4) st[i] = __ldg(&src[idx]);
    }
}
__device__ __forceinline__ void stage_commit(uint32_t* __restrict__ buf,
                                             const float4* st, int tid) {
    float4* dst = (float4*)buf;
#pragma unroll
    for (int i = 0; i < 4; ++i) {
        const int idx = tid + i * NTHREADS;
        if (idx < WHI_W / 4) dst[idx] = st[i];
    }
}

// dst[r][n] = (relu?) x[r][:] . W[:][n] + bias[n].  3-pass bf16:
// hi*hi + hi*lo + lo*hi. B-hi from smem buf, B-lo direct from L2 (g_wlo).
template <bool RELU>
__device__ __forceinline__ void gemm_mma(const uint32_t* __restrict__ xh,
                                         const uint32_t* __restrict__ xl,
                                         const uint32_t* __restrict__ wh,
                                         const uint32_t* __restrict__ wlo,
                                         const float* __restrict__ bias,
                                         float* __restrict__ dst,
                                         int warp, int lane) {
    const int mt = warp >> 2, ng = warp & 3;
    const int g = lane >> 2, t = lane & 3;
    const int r0 = mt * 16, n0 = ng * 32;
    const uint32_t* xa = xh + (r0 + g) * XW + t;
    const uint32_t* xb = xh + (r0 + g + 8) * XW + t;
    const uint32_t* ya = xl + (r0 + g) * XW + t;
    const uint32_t* yb = xl + (r0 + g + 8) * XW + t;
    const uint2* lop = (const uint2*)wlo;   // uint2 idx = (ks*16+nb)*32 + lane

    float d[4][4] = {};
    uint2 blo[4];
#pragma unroll
    for (int ns = 0; ns < 4; ++ns)
        blo[ns] = __ldg(&lop[((ng * 4 + ns) << 5) + lane]);

#pragma unroll
    for (int ks = 0; ks < 8; ++ks) {
        uint2 bln[4];
        if (ks < 7) {
#pragma unroll
            for (int ns = 0; ns < 4; ++ns)
                bln[ns] = __ldg(&lop[(((ks + 1) * 16 + ng * 4 + ns) << 5) + lane]);
        }
        const int kb = ks * 8;
        uint32_t ah[4], al[4];
        ah[0] = xa[kb]; ah[1] = xb[kb]; ah[2] = xa[kb + 4]; ah[3] = xb[kb + 4];
        al[0] = ya[kb]; al[1] = yb[kb]; al[2] = ya[kb + 4]; al[3] = yb[kb + 4];
#pragma unroll
        for (int ns = 0; ns < 4; ++ns) {
            const int cw = (n0 + ns * 8 + g) * WW + kb;
            uint32_t bh[2], bl2[2];
            bh[0] = wh[cw + t]; bh[1] = wh[cw + t + 4];
            bl2[0] = blo[ns].x; bl2[1] = blo[ns].y;
            mma_bf16(d[ns], ah, bh);
            mma_bf16(d[ns], ah, bl2);
            mma_bf16(d[ns], al, bh);
        }
        if (ks < 7) {
#pragma unroll
            for (int ns = 0; ns < 4; ++ns) blo[ns] = bln[ns];
        }
    }
    const int ra = r0 + g, rb = r0 + g + 8;
    const bool va = ra < ROWS, vb = rb < ROWS;
#pragma unroll
    for (int ns = 0; ns < 4; ++ns) {
        const int c = n0 + ns * 8 + 2 * t;
        const float b0 = __ldg(&bias[c]), b1 = __ldg(&bias[c + 1]);
        float v0 = d[ns][0] + b0, v1 = d[ns][1] + b1;
        float v2 = d[ns][2] + b0, v3 = d[ns][3] + b1;
        if (RELU) {
            v0 = fmaxf(v0, 0.f); v1 = fmaxf(v1, 0.f);
            v2 = fmaxf(v2, 0.f); v3 = fmaxf(v3, 0.f);
        }
        float2 p0; p0.x = v0; p0.y = v1;
        float2 p1; p1.x = v2; p1.y = v3;
        if (va) *(float2*)&dst[ra * AS + c] = p0;
        if (vb) *(float2*)&dst[rb * AS + c] = p1;
    }
}

// x[r] = LN(x[r] + add[r]) * g + b, with fused bf16 split. add stride AS.
__device__ __forceinline__ void ln_add_split(float* __restrict__ sx,
                                             const float* __restrict__ add,
                                             const float* __restrict__ g,
                                             const float* __restrict__ b,
                                             uint32_t* __restrict__ xh,
                                             uint32_t* __restrict__ xl,
                                             int warp, int lane) {
    const int c = lane * 4;
    const float4 gv = *(const float4*)&g[c];
    const float4 bvec = *(const float4*)&b[c];
    for (int r = warp; r < ROWS; r += NWARPS) {
        const float4 xv = *(const float4*)&sx[r * D + c];
        const float4 av = *(const float4*)&add[r * AS + c];
        float4 t;
        t.x = xv.x + av.x; t.y = xv.y + av.y; t.z = xv.z + av.z; t.w = xv.w + av.w;
        float s  = t.x + t.y + t.z + t.w;
        float sq = t.x * t.x + t.y * t.y + t.z * t.z + t.w * t.w;
#pragma unroll
        for (int o = 16; o; o >>= 1) {
            s  += __shfl_xor_sync(0xFFFFFFFFu, s,  o);
            sq += __shfl_xor_sync(0xFFFFFFFFu, sq, o);
        }
        const float mu  = s * (1.0f / D);
        const float var = sq * (1.0f / D) - mu * mu;
        const float inv = rsqrtf(var + EPS);
        float4 o4;
        o4.x = (t.x - mu) * inv * gv.x + bvec.x;
        o4.y = (t.y - mu) * inv * gv.y + bvec.y;
        o4.z = (t.z - mu) * inv * gv.z + bvec.z;
        o4.w = (t.w - mu) * inv * gv.w + bvec.w;
        *(float4*)&sx[r * D + c] = o4;
        store_split4(xh, xl, r, c, o4);
    }
}

// ---------------------------------------------------------------------------
__global__ __launch_bounds__(NTHREADS, 1)
void artistbert_kernel(const float* __restrict__ X,    const float* __restrict__ mask_in,
                       const float* __restrict__ seg_in,
                       const float* __restrict__ We,   const float* __restrict__ be,
                       const float* __restrict__ Wp,   const float* __restrict__ bp,
                       const float* __restrict__ Wsg,  const float* __restrict__ bsg,
                       const float* __restrict__ g1,   const float* __restrict__ b1,
                       const float* __restrict__ bq,   const float* __restrict__ bk,
                       const float* __restrict__ bv,
                       const float* __restrict__ g2,   const float* __restrict__ b2,
                       const float* __restrict__ bd,
                       const float* __restrict__ Wo,   const float* __restrict__ bo,
                       float* __restrict__ out) {
    extern __shared__ float sm[];
    float*    sx    = sm + OFF_SX;
    float*    sa    = sm + OFF_SA;
    float*    sb    = sm + OFF_SB;
    uint32_t* xh    = (uint32_t*)(sm + OFF_XH);
    uint32_t* xl    = (uint32_t*)(sm + OFF_XL);
    uint32_t* whA   = (uint32_t*)(sm + OFF_WHA);
    uint32_t* whB   = (uint32_t*)(sm + OFF_WHB);
    float*    ss    = sm + OFF_SC;
    float*    smask = sm + OFF_M;
    float*    sseg  = sm + OFF_SEG;

    const int tid  = threadIdx.x;
    const int warp = tid >> 5;
    const int lane = tid & 31;
    const int c4   = lane * 4;
    const int wb   = warp / 5;          // batch for scores/attn tiling
    const int wsub = warp - wb * 5;     // sub-warp
    const int  b0       = blockIdx.x * BQ;
    const long base_row = (long)b0 * S;
    float4 st[4];

    // zero xh/xl (incl. pad rows 68-79)
    for (int i = tid; i < 80 * XW; i += NTHREADS) { xh[i] = 0u; xl[i] = 0u; }

    // ---- stage embedding tables + per-tile inputs (We in sa region) ----
    float* swe = sa + S * D + NSEG * D;
    for (int i = tid; i < S * D; i += NTHREADS) {
        const int d = i & (D - 1);
        sa[i] = Wp[i] + bp[d] + be[d] + bsg[d];
    }
    for (int i = tid; i < NSEG * D; i += NTHREADS) sa[S * D + i] = Wsg[i];
    for (int i = tid; i < V * D; i += NTHREADS) swe[i] = We[i];
    {
        const float* Xb = X + base_row * V;
        for (int i = tid; i < ROWS * V; i += NTHREADS) sb[i] = Xb[i];
    }
    for (int i = tid; i < ROWS; i += NTHREADS) smask[i] = mask_in[base_row + i];
    {
        const float* Sg = seg_in + base_row * NSEG;
        for (int i = tid; i < ROWS * NSEG; i += NTHREADS) sseg[i] = Sg[i];
    }
    __syncthreads();

    // ---- embedding + fused split; prefetch/commit Wq(layer 0) -> whA ----
    stage_prefetch(0, st, tid);
    for (int r = warp; r < ROWS; r += NWARPS) {
        const int s = r % S;
        float4 acc = *(const float4*)&sa[s * D + c4];
#pragma unroll
        for (int j = 0; j < NSEG; ++j) {
            const float svv = sseg[r * NSEG + j];
            const float4 wv = *(const float4*)&sa[S * D + j * D + c4];
            FMA4(acc, svv, wv)
        }
        const float* xr = &sb[r * V];
#pragma unroll
        for (int vtok = 0; vtok < V; ++vtok) {
            const float xv = xr[vtok];
            const float4 wv = *(const float4*)&swe[vtok * D + c4];
            FMA4(acc, xv, wv)
        }
        *(float4*)&sx[r * D + c4] = acc;
        store_split4(xh, xl, r, c4, acc);
    }
    stage_commit(whA, st, tid);
    __syncthreads();

    // ---- transformer layers ----
    for (int li = 0; li < NL; ++li) {
        const int base = li * 4;

        // P1: gemmQ(whA) || stage Wk -> whB
        stage_prefetch(base + 1, st, tid);
        gemm_mma<true>(xh, xl, whA, g_wlo + (size_t)(base + 0) * WLO_W,
                       bq + li * D, sa, warp, lane);
        stage_commit(whB, st, tid);
        __syncthreads();

        // P2: gemmK(whB) || stage Wv -> whA
        stage_prefetch(base + 2, st, tid);
        gemm_mma<true>(xh, xl, whB, g_wlo + (size_t)(base + 1) * WLO_W,
                       bk + li * D, sb, warp, lane);
        stage_commit(whA, st, tid);
        __syncthreads();

        // P3: scores + warp softmax
        {
            float4 qf[4];
#pragma unroll
            for (int t = 0; t < 4; ++t) {
                const int row = wsub + 5 * t;
                qf[t] = (row < S) ? *(const float4*)&sa[(wb * S + row) * AS + c4]
                                  : make_float4(0.f, 0.f, 0.f, 0.f);
            }
            for (int ki = 0; ki < S; ++ki) {
                const float4 kv = *(const float4*)&sb[(wb * S + ki) * AS + c4];
#pragma unroll
                for (int t = 0; t < 4; ++t) {
                    const int row = wsub + 5 * t;
                    if (row < S) {
                        float p = qf[t].x * kv.x + qf[t].y * kv.y
                                + qf[t].z * kv.z + qf[t].w * kv.w;
#pragma unroll
                        for (int o = 16; o; o >>= 1) p += __shfl_xor_sync(0xFFFFFFFFu, p, o);
                        if (lane == 0) ss[wb * S * S + row * S + ki] = p;
                    }
                }
            }
#pragma unroll
            for (int t = 0; t < 4; ++t) {
                const int row = wsub + 5 * t;
                if (row < S) {
                    float* rp = &ss[wb * S * S + row * S];
                    const float v = (lane < S) ? rp[lane] : -3.0e38f;
                    float mxv = v;
#pragma unroll
                    for (int o = 16; o; o >>= 1) mxv = fmaxf(mxv, __shfl_xor_sync(0xFFFFFFFFu, mxv, o));
                    const float e = (lane < S) ? __expf(v - mxv) : 0.f;
                    float sv = e;
#pragma unroll
                    for (int o = 16; o; o >>= 1) sv += __shfl_xor_sync(0xFFFFFFFFu, sv, o);
                    if (lane < S) rp[lane] = __fdividef(e, sv);
                }
            }
        }
        __syncthreads();

        // P4: gemmV(whA) || stage Wd -> whB
        stage_prefetch(base + 3, st, tid);
        gemm_mma<true>(xh, xl, whA, g_wlo + (size_t)(base + 2) * WLO_W,
                       bv + li * D, sa, warp, lane);
        stage_commit(whB, st, tid);
        __syncthreads();

        // P5: attn + mask + residual + LN1 + split (fused)
        {
            float4 acc[4];
#pragma unroll
            for (int t = 0; t < 4; ++t) acc[t] = make_float4(0.f, 0.f, 0.f, 0.f);
            for (int ki = 0; ki < S; ++ki) {
                const float4 vv = *(const float4*)&sa[(wb * S + ki) * AS + c4];
#pragma unroll
                for (int t = 0; t < 4; ++t) {
                    const int row = wsub + 5 * t;
                    if (row < S) {
                        const float pv = ss[wb * S * S + row * S + ki];
                        FMA4(acc[t], pv, vv)
                    }
                }
            }
            const float4 gv = *(const float4*)&g1[li * D + c4];
            const float4 bvec = *(const float4*)&b1[li * D + c4];
#pragma unroll
            for (int t = 0; t < 4; ++t) {
                const int row = wsub + 5 * t;
                if (row < S) {
                    const int r = wb * S + row;
                    const float mk = smask[r];
                    const float4 xv = *(const float4*)&sx[r * D + c4];
                    float4 u;
                    u.x = xv.x + acc[t].x * mk; u.y = xv.y + acc[t].y * mk;
                    u.z = xv.z + acc[t].z * mk; u.w = xv.w + acc[t].w * mk;
                    float s  = u.x + u.y + u.z + u.w;
                    float sq = u.x * u.x + u.y * u.y + u.z * u.z + u.w * u.w;
#pragma unroll
                    for (int o = 16; o; o >>= 1) {
                        s  += __shfl_xor_sync(0xFFFFFFFFu, s,  o);
                        sq += __shfl_xor_sync(0xFFFFFFFFu, sq, o);
                    }
                    const float mu  = s * (1.0f / D);
                    const float var = sq * (1.0f / D) - mu * mu;
                    const float inv = rsqrtf(var + EPS);
                    float4 o4;
                    o4.x = (u.x - mu) * inv * gv.x + bvec.x;
                    o4.y = (u.y - mu) * inv * gv.y + bvec.y;
                    o4.z = (u.z - mu) * inv * gv.z + bvec.z;
                    o4.w = (u.w - mu) * inv * gv.w + bvec.w;
                    *(float4*)&sx[r * D + c4] = o4;
                    store_split4(xh, xl, r, c4, o4);
                }
            }
        }
        __syncthreads();

        // P6: gemmD(whB) || stage next-layer Wq -> whA
        if (li + 1 < NL) stage_prefetch(base + 4, st, tid);
        gemm_mma<false>(xh, xl, whB, g_wlo + (size_t)(base + 3) * WLO_W,
                        bd + li * D, sa, warp, lane);
        if (li + 1 < NL) stage_commit(whA, st, tid);
        __syncthreads();

        // P7: x = LN(x + d) + split
        ln_add_split(sx, sa, g2 + li * D, b2 + li * D, xh, xl, warp, lane);
        __syncthreads();
    }

    // ---- output projection: out = x@Wo + bo (fp32 SIMT) ----
    float* swb = sm + OFF_WHA;
    for (int i = tid; i < D * 32; i += NTHREADS) {
        const int k = i >> 5, n = i & 31;
        swb[i] = (n < V) ? Wo[k * V + n] : 0.f;
    }
    __syncthreads();
    for (int r = warp; r < ROWS; r += NWARPS) {
        if (lane < V) {
            float acc = bo[lane];
            const float* xr = &sx[r * D];
#pragma unroll 8
            for (int k = 0; k < D; ++k) acc += xr[k] * swb[k * 32 + lane];
            out[(base_row + r) * V + lane] = acc;
        }
    }
}

// ---------------------------------------------------------------------------
extern "C" void kernel_launch(void* const* d_in, const int* in_sizes, int n_in,
                              void* d_out, int out_size) {
    (void)in_sizes; (void)n_in; (void)out_size;
    const float* X    = (const float*)d_in[0];
    const float* mask = (const float*)d_in[1];
    const float* seg  = (const float*)d_in[2];
    const float* We   = (const float*)d_in[3];
    const float* be   = (const float*)d_in[4];
    const float* Wp   = (const float*)d_in[5];
    const float* bp   = (const float*)d_in[6];
    const float* Wsg  = (const float*)d_in[7];
    const float* bsg  = (const float*)d_in[8];
    const float* g1   = (const float*)d_in[9];
    const float* b1   = (const float*)d_in[10];
    const float* Wq   = (const float*)d_in[11];
    const float* bq   = (const float*)d_in[12];
    const float* Wk   = (const float*)d_in[13];
    const float* bk   = (const float*)d_in[14];
    const float* Wv   = (const float*)d_in[15];
    const float* bv   = (const float*)d_in[16];
    const float* g2   = (const float*)d_in[17];
    const float* b2   = (const float*)d_in[18];
    const float* Wd   = (const float*)d_in[19];
    const float* bd   = (const float*)d_in[20];
    const float* Wo   = (const float*)d_in[21];
    const float* bo   = (const float*)d_in[22];
    float* out = (float*)d_out;

    bake_kernel<<<(NL * 4 * 64 * D + 255) / 256, 256>>>(Wq, Wk, Wv, Wd);

    cudaFuncSetAttribute(artistbert_kernel,
                         cudaFuncAttributeMaxDynamicSharedMemorySize, SMEM_BYTES);
    artistbert_kernel<<<BB / BQ, NTHREADS, SMEM_BYTES>>>(
        X, mask, seg, We, be, Wp, bp, Wsg, bsg, g1, b1,
        bq, bk, bv, g2, b2, bd, Wo, bo, out);
}